// round 3
// baseline (speedup 1.0000x reference)
#include <cuda_runtime.h>
#include <math.h>

// ---------------- problem constants ----------------
#define BATCH   32
#define ETOT    262144          // 32*1024*8 edges (fixed; masked via ew)
#define NMAX    32768           // max nodes (layer 1)
#define K1      615             // ceil(0.6*1024)
#define K2      369             // ceil(0.6*615)
#define K3      185             // ceil(0.5*369)
#define N1      32768
#define N2      (BATCH*K1)      // 19680
#define N3      (BATCH*K2)      // 11808
#define N4      (BATCH*K3)      // 5920

#define CEILDIV(a,b) (((a)+(b)-1)/(b))

// ---------------- static device scratch (no allocs allowed) ----------------
__device__ float g_buf0[(size_t)NMAX * 512];
__device__ float g_buf1[(size_t)NMAX * 512];
__device__ float g_deg[NMAX];
__device__ float g_dis[NMAX];
__device__ float g_score[NMAX];
__device__ float g_t[NMAX];
__device__ float g_gain[NMAX];
__device__ int   g_newid[NMAX];
__device__ int   g_perm[NMAX];
__device__ int   g_src[ETOT];
__device__ int   g_dst[ETOT];
__device__ float g_ew[ETOT];
__device__ float g_sum[512];
__device__ float g_sumsq[512];

// ---------------- kernels ----------------

__global__ void edge_init_kernel(const int* __restrict__ ei,
                                 int* __restrict__ src, int* __restrict__ dst,
                                 float* __restrict__ ew) {
    int e = blockIdx.x * blockDim.x + threadIdx.x;
    if (e >= ETOT) return;
    src[e] = ei[e];
    dst[e] = ei[ETOT + e];
    ew[e]  = 1.0f;
}

// Classic 128x128x8 register-tiled SGEMM: C[M,N] = A[M,K] @ B[K,N]
#define BM 128
#define BN 128
#define BK 8
#define TM 8
#define TN 8
__global__ void __launch_bounds__(256)
gemm_kernel(const float* __restrict__ A, const float* __restrict__ B,
            float* __restrict__ C, int M, int K, int N) {
    __shared__ float As[BK][BM];
    __shared__ float Bs[BK][BN];
    const int tid = threadIdx.x;
    const int tx = tid % (BN / TN);     // 0..15
    const int ty = tid / (BN / TN);     // 0..15
    const int mBase = blockIdx.y * BM;
    const int nBase = blockIdx.x * BN;

    const int arow = tid >> 1;          // 0..127
    const int acol = (tid & 1) * 4;     // 0 or 4
    const int brow = tid >> 5;          // 0..7
    const int bcol = (tid & 31) * 4;    // 0..124

    float acc[TM][TN];
#pragma unroll
    for (int i = 0; i < TM; i++)
#pragma unroll
        for (int j = 0; j < TN; j++) acc[i][j] = 0.f;

    for (int k0 = 0; k0 < K; k0 += BK) {
        int gm = mBase + arow;
        float4 av = make_float4(0.f, 0.f, 0.f, 0.f);
        if (gm < M) av = *(const float4*)(A + (size_t)gm * K + k0 + acol);
        As[acol + 0][arow] = av.x;
        As[acol + 1][arow] = av.y;
        As[acol + 2][arow] = av.z;
        As[acol + 3][arow] = av.w;
        float4 bv = *(const float4*)(B + (size_t)(k0 + brow) * N + nBase + bcol);
        *(float4*)&Bs[brow][bcol] = bv;
        __syncthreads();
#pragma unroll
        for (int kk = 0; kk < BK; kk++) {
            float a[TM], b[TN];
#pragma unroll
            for (int i = 0; i < TM; i++) a[i] = As[kk][ty * TM + i];
#pragma unroll
            for (int j = 0; j < TN; j++) b[j] = Bs[kk][tx * TN + j];
#pragma unroll
            for (int i = 0; i < TM; i++)
#pragma unroll
                for (int j = 0; j < TN; j++) acc[i][j] += a[i] * b[j];
        }
        __syncthreads();
    }
#pragma unroll
    for (int i = 0; i < TM; i++) {
        int row = mBase + ty * TM + i;
        if (row < M) {
            float* cp = C + (size_t)row * N + nBase + tx * TN;
#pragma unroll
            for (int j = 0; j < TN; j++) cp[j] = acc[i][j];
        }
    }
}

__global__ void deg_kernel(const int* __restrict__ dst, const float* __restrict__ ew,
                           float* __restrict__ deg) {
    int e = blockIdx.x * blockDim.x + threadIdx.x;
    if (e >= ETOT) return;
    float w = ew[e];
    if (w != 0.f) atomicAdd(&deg[dst[e]], w);
}

__global__ void dis_kernel(const float* __restrict__ deg, float* __restrict__ dis, int n) {
    int i = blockIdx.x * blockDim.x + threadIdx.x;
    if (i >= n) return;
    float d = deg[i];
    dis[i] = (d > 0.f) ? rsqrtf(fmaxf(d, 1e-12f)) : 0.f;
}

__global__ void bias_init_kernel(float* __restrict__ out, const float* __restrict__ b,
                                 int n, int C) {
    int idx = blockIdx.x * blockDim.x + threadIdx.x;
    if (idx >= n * C) return;
    out[idx] = b[idx % C];
}

// warp per edge; lanes cover channels (float4 granularity)
__global__ void scatter_kernel(const float* __restrict__ h, float* __restrict__ out,
                               const int* __restrict__ src, const int* __restrict__ dst,
                               const float* __restrict__ ew, const float* __restrict__ dis,
                               int C4) {
    int warp = (blockIdx.x * blockDim.x + threadIdx.x) >> 5;
    int lane = threadIdx.x & 31;
    if (warp >= ETOT) return;
    float w = ew[warp];
    if (w == 0.f) return;
    int s = src[warp], d = dst[warp];
    float nm = dis[s] * dis[d] * w;
    const float4* hs = (const float4*)(h + (size_t)s * (C4 * 4));
    float* o = out + (size_t)d * (C4 * 4);
    for (int c = lane; c < C4; c += 32) {
        float4 v = hs[c];
        atomicAdd(o + c * 4 + 0, v.x * nm);
        atomicAdd(o + c * 4 + 1, v.y * nm);
        atomicAdd(o + c * 4 + 2, v.z * nm);
        atomicAdd(o + c * 4 + 3, v.w * nm);
    }
}

// per-channel sum / sumsq over rows; grid = (C/256, rowSplits)
__global__ void bn_stats_kernel(const float* __restrict__ h,
                                float* __restrict__ sum, float* __restrict__ sumsq,
                                int n, int C) {
    int c = blockIdx.x * 256 + threadIdx.x;
    if (c >= C) return;
    int rowsPer = CEILDIV(n, gridDim.y);
    int r0 = blockIdx.y * rowsPer;
    int r1 = min(n, r0 + rowsPer);
    float s = 0.f, sq = 0.f;
    for (int r = r0; r < r1; r++) {
        float v = h[(size_t)r * C + c];
        s += v;
        sq += v * v;
    }
    atomicAdd(&sum[c], s);
    atomicAdd(&sumsq[c], sq);
}

__global__ void bn_apply_kernel(float* __restrict__ h,
                                const float* __restrict__ sum, const float* __restrict__ sumsq,
                                const float* __restrict__ gma, const float* __restrict__ bta,
                                int n, int C) {
    int idx = blockIdx.x * blockDim.x + threadIdx.x;
    if (idx >= n * C) return;
    int c = idx % C;
    float invn = 1.f / (float)n;
    float mean = sum[c] * invn;
    float var = sumsq[c] * invn - mean * mean;
    float y = (h[idx] - mean) * rsqrtf(var + 1e-5f) * gma[c] + bta[c];
    h[idx] = tanhf(y);
}

// per-node dot(h, rel_w) and dot(h, root_w); warp per node
__global__ void node_dots_kernel(const float* __restrict__ h,
                                 const float* __restrict__ relw,
                                 const float* __restrict__ rootw,
                                 const float* __restrict__ relb,
                                 float* __restrict__ t, float* __restrict__ score,
                                 int n, int C) {
    int node = (blockIdx.x * blockDim.x + threadIdx.x) >> 5;
    int lane = threadIdx.x & 31;
    if (node >= n) return;
    const float* hp = h + (size_t)node * C;
    float a = 0.f, b = 0.f;
    for (int c = lane; c < C; c += 32) {
        float v = hp[c];
        a += v * relw[c];
        b += v * rootw[c];
    }
#pragma unroll
    for (int o = 16; o > 0; o >>= 1) {
        a += __shfl_down_sync(0xffffffffu, a, o);
        b += __shfl_down_sync(0xffffffffu, b, o);
    }
    if (lane == 0) {
        t[node] = a;
        score[node] = b + relb[0];
    }
}

__global__ void score_edge_kernel(const int* __restrict__ src, const int* __restrict__ dst,
                                  const float* __restrict__ ew, const float* __restrict__ t,
                                  float* __restrict__ score) {
    int e = blockIdx.x * blockDim.x + threadIdx.x;
    if (e >= ETOT) return;
    float w = ew[e];
    if (w != 0.f) atomicAdd(&score[dst[e]], w * t[src[e]]);
}

__global__ void init_newid_kernel(int* __restrict__ newid, int n) {
    int i = blockIdx.x * blockDim.x + threadIdx.x;
    if (i < n) newid[i] = -1;
}

// Per-graph top-k via bitonic sort of (score desc, idx asc) — matches jax.lax.top_k order.
template <int SZ>
__global__ void __launch_bounds__(512)
topk_kernel(const float* __restrict__ score, int n_per, int ksel,
            int* __restrict__ perm, float* __restrict__ gain, int* __restrict__ newid) {
    __shared__ float sk[SZ];
    __shared__ int si[SZ];
    const int g = blockIdx.x;
    const int tid = threadIdx.x;
    for (int i = tid; i < SZ; i += 512) {
        if (i < n_per) { sk[i] = score[g * n_per + i]; si[i] = i; }
        else           { sk[i] = -INFINITY;            si[i] = 0x40000000 + i; }
    }
    __syncthreads();
    for (int kk = 2; kk <= SZ; kk <<= 1) {
        for (int j = kk >> 1; j > 0; j >>= 1) {
            for (int i = tid; i < SZ; i += 512) {
                int ixj = i ^ j;
                if (ixj > i) {
                    bool up = ((i & kk) == 0);
                    float s1 = sk[i], s2 = sk[ixj];
                    int i1 = si[i], i2 = si[ixj];
                    bool after = (s1 < s2) || (s1 == s2 && i1 > i2);
                    if (up == after) {
                        sk[i] = s2; sk[ixj] = s1;
                        si[i] = i2; si[ixj] = i1;
                    }
                }
            }
            __syncthreads();
        }
    }
    for (int r = tid; r < ksel; r += 512) {
        int old = g * n_per + si[r];
        int ng = g * ksel + r;
        perm[ng] = old;
        gain[ng] = tanhf(sk[r]);
        newid[old] = ng;
    }
}

__global__ void gather_kernel(const float* __restrict__ hin, float* __restrict__ hout,
                              const int* __restrict__ perm, const float* __restrict__ gain,
                              int rows, int C4) {
    int idx = blockIdx.x * blockDim.x + threadIdx.x;
    if (idx >= rows * C4) return;
    int row = idx / C4;
    int c = idx - row * C4;
    float gn = gain[row];
    float4 v = ((const float4*)hin)[(size_t)perm[row] * C4 + c];
    v.x *= gn; v.y *= gn; v.z *= gn; v.w *= gn;
    ((float4*)hout)[idx] = v;
}

__global__ void remap_kernel(int* __restrict__ src, int* __restrict__ dst,
                             float* __restrict__ ew, const int* __restrict__ newid) {
    int e = blockIdx.x * blockDim.x + threadIdx.x;
    if (e >= ETOT) return;
    int ns = newid[src[e]];
    int nd = newid[dst[e]];
    bool keep = (ns >= 0) && (nd >= 0);
    src[e] = keep ? ns : 0;
    dst[e] = keep ? nd : 0;
    ew[e] = keep ? ew[e] : 0.f;
}

__global__ void readout_kernel(const float* __restrict__ h, float* __restrict__ out) {
    int g = blockIdx.x;
    int c = threadIdx.x;  // 256 threads, C=256
    const float* p = h + (size_t)(g * K3) * 256 + c;
    float mx = -INFINITY, sm = 0.f;
    for (int i = 0; i < K3; i++) {
        float v = p[(size_t)i * 256];
        mx = fmaxf(mx, v);
        sm += v;
    }
    out[g * 512 + c] = mx;
    out[g * 512 + 256 + c] = sm / (float)K3;
}

// ---------------- host orchestration ----------------

extern "C" void kernel_launch(void* const* d_in, const int* in_sizes, int n_in,
                              void* d_out, int out_size) {
    const float* x    = (const float*)d_in[0];
    const int*   ei   = (const int*)d_in[1];
    const float* W1   = (const float*)d_in[2];
    const float* b1   = (const float*)d_in[3];
    const float* W2   = (const float*)d_in[4];
    const float* b2   = (const float*)d_in[5];
    const float* W3   = (const float*)d_in[6];
    const float* b3   = (const float*)d_in[7];
    const float* W4   = (const float*)d_in[8];
    const float* b4   = (const float*)d_in[9];
    const float* g1   = (const float*)d_in[10];
    const float* be1  = (const float*)d_in[11];
    const float* g2   = (const float*)d_in[12];
    const float* be2  = (const float*)d_in[13];
    const float* g3   = (const float*)d_in[14];
    const float* be3  = (const float*)d_in[15];
    const float* p1rw = (const float*)d_in[16];
    const float* p1rb = (const float*)d_in[17];
    const float* p1ow = (const float*)d_in[18];
    const float* p2rw = (const float*)d_in[19];
    const float* p2rb = (const float*)d_in[20];
    const float* p2ow = (const float*)d_in[21];
    const float* p3rw = (const float*)d_in[22];
    const float* p3rb = (const float*)d_in[23];
    const float* p3ow = (const float*)d_in[24];
    float* out = (float*)d_out;

    float *buf0, *buf1, *deg, *dis, *score, *t, *gain, *ew, *sum, *sumsq;
    int *src, *dst, *newid, *perm;
    cudaGetSymbolAddress((void**)&buf0, g_buf0);
    cudaGetSymbolAddress((void**)&buf1, g_buf1);
    cudaGetSymbolAddress((void**)&deg, g_deg);
    cudaGetSymbolAddress((void**)&dis, g_dis);
    cudaGetSymbolAddress((void**)&score, g_score);
    cudaGetSymbolAddress((void**)&t, g_t);
    cudaGetSymbolAddress((void**)&gain, g_gain);
    cudaGetSymbolAddress((void**)&ew, g_ew);
    cudaGetSymbolAddress((void**)&sum, g_sum);
    cudaGetSymbolAddress((void**)&sumsq, g_sumsq);
    cudaGetSymbolAddress((void**)&src, g_src);
    cudaGetSymbolAddress((void**)&dst, g_dst);
    cudaGetSymbolAddress((void**)&newid, g_newid);
    cudaGetSymbolAddress((void**)&perm, g_perm);

    const int EB = CEILDIV(ETOT, 256);              // edge-parallel grid (blocks)
    const int SCATTER_BLOCKS = CEILDIV(ETOT * 32, 256);  // warp-per-edge: 32768 blocks

    edge_init_kernel<<<EB, 256>>>(ei, src, dst, ew);

    auto gcn = [&](const float* in, float* hbuf, float* aggbuf,
                   int n, int Cin, int Cout,
                   const float* W, const float* b) {
        gemm_kernel<<<dim3(Cout / BN, CEILDIV(n, BM)), 256>>>(in, W, hbuf, n, Cin, Cout);
        cudaMemsetAsync(deg, 0, (size_t)n * sizeof(float));
        deg_kernel<<<EB, 256>>>(dst, ew, deg);
        dis_kernel<<<CEILDIV(n, 256), 256>>>(deg, dis, n);
        bias_init_kernel<<<CEILDIV(n * Cout, 256), 256>>>(aggbuf, b, n, Cout);
        scatter_kernel<<<SCATTER_BLOCKS, 256>>>(hbuf, aggbuf, src, dst, ew, dis, Cout / 4);
    };
    auto bn_tanh = [&](float* hbuf, int n, int C, const float* gma, const float* bta) {
        cudaMemsetAsync(sum, 0, C * sizeof(float));
        cudaMemsetAsync(sumsq, 0, C * sizeof(float));
        bn_stats_kernel<<<dim3(CEILDIV(C, 256), 64), 256>>>(hbuf, sum, sumsq, n, C);
        bn_apply_kernel<<<CEILDIV(n * C, 256), 256>>>(hbuf, sum, sumsq, gma, bta, n, C);
    };
    auto pool_pre = [&](const float* hbuf, int n, int C,
                        const float* rw, const float* rb, const float* ow) {
        node_dots_kernel<<<CEILDIV(n * 32, 256), 256>>>(hbuf, rw, ow, rb, t, score, n, C);
        score_edge_kernel<<<EB, 256>>>(src, dst, ew, t, score);
        init_newid_kernel<<<CEILDIV(n, 256), 256>>>(newid, n);
    };
    auto pool_post = [&](const float* hbuf, float* outbuf, int ksel, int C) {
        int rows = BATCH * ksel;
        gather_kernel<<<CEILDIV(rows * (C / 4), 256), 256>>>(hbuf, outbuf, perm, gain,
                                                             rows, C / 4);
        remap_kernel<<<EB, 256>>>(src, dst, ew, newid);
    };

    // ---------- Layer 1 ----------
    gcn(x, buf1, buf0, N1, 512, 512, W1, b1);
    bn_tanh(buf0, N1, 512, g1, be1);
    pool_pre(buf0, N1, 512, p1rw, p1rb, p1ow);
    topk_kernel<1024><<<BATCH, 512>>>(score, 1024, K1, perm, gain, newid);
    pool_post(buf0, buf1, K1, 512);

    // ---------- Layer 2 ----------
    gcn(buf1, buf0, buf1, N2, 512, 512, W2, b2);
    bn_tanh(buf1, N2, 512, g2, be2);
    pool_pre(buf1, N2, 512, p2rw, p2rb, p2ow);
    topk_kernel<1024><<<BATCH, 512>>>(score, K1, K2, perm, gain, newid);
    pool_post(buf1, buf0, K2, 512);

    // ---------- Layer 3 ----------
    gcn(buf0, buf1, buf0, N3, 512, 256, W3, b3);
    bn_tanh(buf0, N3, 256, g3, be3);
    pool_pre(buf0, N3, 256, p3rw, p3rb, p3ow);
    topk_kernel<512><<<BATCH, 512>>>(score, K2, K3, perm, gain, newid);
    pool_post(buf0, buf1, K3, 256);

    // ---------- Layer 4 (no BN / pool) ----------
    gcn(buf1, buf0, buf1, N4, 256, 256, W4, b4);

    // ---------- readout ----------
    readout_kernel<<<BATCH, 256>>>(buf1, out);
    (void)in_sizes; (void)n_in; (void)out_size;
}

// round 4
// speedup vs baseline: 1.0418x; 1.0418x over previous
#include <cuda_runtime.h>
#include <math.h>

// ---------------- problem constants ----------------
#define BATCH   32
#define ETOT    262144          // 32*1024*8 edges (fixed; masked via ew)
#define NMAX    32768           // max nodes (layer 1)
#define K1      615             // ceil(0.6*1024)
#define K2      369             // ceil(0.6*615)
#define K3      185             // ceil(0.5*369)
#define N1      32768
#define N2      (BATCH*K1)      // 19680
#define N3      (BATCH*K2)      // 11808
#define N4      (BATCH*K3)      // 5920

#define CEILDIV(a,b) (((a)+(b)-1)/(b))

// ---------------- static device scratch (no allocs allowed) ----------------
__device__ float g_buf0[(size_t)NMAX * 512];
__device__ float g_buf1[(size_t)NMAX * 512];
__device__ float g_deg[NMAX];
__device__ float g_dis[NMAX];
__device__ float g_score[NMAX];
__device__ float g_t[NMAX];
__device__ float g_gain[NMAX];
__device__ int   g_newid[NMAX];
__device__ int   g_perm[NMAX];
__device__ int   g_src[ETOT];
__device__ int   g_dst[ETOT];
__device__ float g_ew[ETOT];
__device__ float g_sum[512];
__device__ float g_sumsq[512];

// ---------------- kernels ----------------

__global__ void edge_init_kernel(const int* __restrict__ ei,
                                 int* __restrict__ src, int* __restrict__ dst,
                                 float* __restrict__ ew) {
    int e = blockIdx.x * blockDim.x + threadIdx.x;
    if (e >= ETOT) return;
    src[e] = ei[e];
    dst[e] = ei[ETOT + e];
    ew[e]  = 1.0f;
}

// ---------------------------------------------------------------
// Double-buffered 128x128x16 register-tiled SGEMM.
// C[M,N] = A[M,K] @ B[K,N].  K multiple of 16, N multiple of 128, M guarded.
// 256 threads, TM=TN=8, global loads for tile k+1 staged in registers
// while computing tile k.
// ---------------------------------------------------------------
#define BM 128
#define BN 128
#define BK 16
#define TM 8
#define TN 8
#define BMP 132   // padded leading dim for As (cuts STS conflicts, keeps 16B align)

__global__ void __launch_bounds__(256)
gemm_kernel(const float* __restrict__ A, const float* __restrict__ B,
            float* __restrict__ C, int M, int K, int N) {
    __shared__ float As[2][BK][BMP];
    __shared__ float Bs[2][BK][BN];

    const int tid = threadIdx.x;
    const int tx = tid & 15;            // 0..15
    const int ty = tid >> 4;            // 0..15
    const int mBase = blockIdx.y * BM;
    const int nBase = blockIdx.x * BN;

    // load mapping (each thread moves 2 float4 of A and 2 float4 of B)
    // A tile: 128 rows x 16 cols; float4 id f: row=f>>2 (0..127), col=(f&3)*4
    // B tile: 16 rows x 128 cols; float4 id f: row=f>>5 (0..15), col=(f&31)*4
    const int ar0 = tid >> 2,        ac0 = (tid & 3) * 4;
    const int ar1 = (tid + 256) >> 2, ac1 = ((tid + 256) & 3) * 4;
    const int br0 = tid >> 5,        bc0 = (tid & 31) * 4;
    const int br1 = (tid + 256) >> 5, bc1 = ((tid + 256) & 31) * 4;

    float acc[TM][TN];
#pragma unroll
    for (int i = 0; i < TM; i++)
#pragma unroll
        for (int j = 0; j < TN; j++) acc[i][j] = 0.f;

    const float4 z4 = make_float4(0.f, 0.f, 0.f, 0.f);

    // ---- prologue: load tile 0 into buffer 0 ----
    {
        int gm0 = mBase + ar0, gm1 = mBase + ar1;
        float4 a0 = (gm0 < M) ? *(const float4*)(A + (size_t)gm0 * K + ac0) : z4;
        float4 a1 = (gm1 < M) ? *(const float4*)(A + (size_t)gm1 * K + ac1) : z4;
        float4 b0 = *(const float4*)(B + (size_t)br0 * N + nBase + bc0);
        float4 b1 = *(const float4*)(B + (size_t)br1 * N + nBase + bc1);
        As[0][ac0 + 0][ar0] = a0.x; As[0][ac0 + 1][ar0] = a0.y;
        As[0][ac0 + 2][ar0] = a0.z; As[0][ac0 + 3][ar0] = a0.w;
        As[0][ac1 + 0][ar1] = a1.x; As[0][ac1 + 1][ar1] = a1.y;
        As[0][ac1 + 2][ar1] = a1.z; As[0][ac1 + 3][ar1] = a1.w;
        *(float4*)&Bs[0][br0][bc0] = b0;
        *(float4*)&Bs[0][br1][bc1] = b1;
    }
    __syncthreads();

    int buf = 0;
    for (int k0 = 0; k0 < K; k0 += BK, buf ^= 1) {
        const int kn = k0 + BK;
        const bool hasNext = kn < K;
        float4 sa0, sa1, sb0, sb1;
        if (hasNext) {
            int gm0 = mBase + ar0, gm1 = mBase + ar1;
            sa0 = (gm0 < M) ? *(const float4*)(A + (size_t)gm0 * K + kn + ac0) : z4;
            sa1 = (gm1 < M) ? *(const float4*)(A + (size_t)gm1 * K + kn + ac1) : z4;
            sb0 = *(const float4*)(B + (size_t)(kn + br0) * N + nBase + bc0);
            sb1 = *(const float4*)(B + (size_t)(kn + br1) * N + nBase + bc1);
        }
#pragma unroll
        for (int kk = 0; kk < BK; kk++) {
            float4 a0 = *(const float4*)&As[buf][kk][ty * TM];
            float4 a1 = *(const float4*)&As[buf][kk][ty * TM + 4];
            float4 b0 = *(const float4*)&Bs[buf][kk][tx * TN];
            float4 b1 = *(const float4*)&Bs[buf][kk][tx * TN + 4];
            float a[TM] = {a0.x, a0.y, a0.z, a0.w, a1.x, a1.y, a1.z, a1.w};
            float b[TN] = {b0.x, b0.y, b0.z, b0.w, b1.x, b1.y, b1.z, b1.w};
#pragma unroll
            for (int i = 0; i < TM; i++)
#pragma unroll
                for (int j = 0; j < TN; j++) acc[i][j] += a[i] * b[j];
        }
        if (hasNext) {
            int nb = buf ^ 1;
            As[nb][ac0 + 0][ar0] = sa0.x; As[nb][ac0 + 1][ar0] = sa0.y;
            As[nb][ac0 + 2][ar0] = sa0.z; As[nb][ac0 + 3][ar0] = sa0.w;
            As[nb][ac1 + 0][ar1] = sa1.x; As[nb][ac1 + 1][ar1] = sa1.y;
            As[nb][ac1 + 2][ar1] = sa1.z; As[nb][ac1 + 3][ar1] = sa1.w;
            *(float4*)&Bs[nb][br0][bc0] = sb0;
            *(float4*)&Bs[nb][br1][bc1] = sb1;
            __syncthreads();
        }
    }

#pragma unroll
    for (int i = 0; i < TM; i++) {
        int row = mBase + ty * TM + i;
        if (row < M) {
            float* cp = C + (size_t)row * N + nBase + tx * TN;
            float4 v0 = make_float4(acc[i][0], acc[i][1], acc[i][2], acc[i][3]);
            float4 v1 = make_float4(acc[i][4], acc[i][5], acc[i][6], acc[i][7]);
            *(float4*)(cp) = v0;
            *(float4*)(cp + 4) = v1;
        }
    }
}

__global__ void deg_kernel(const int* __restrict__ dst, const float* __restrict__ ew,
                           float* __restrict__ deg) {
    int e = blockIdx.x * blockDim.x + threadIdx.x;
    if (e >= ETOT) return;
    float w = ew[e];
    if (w != 0.f) atomicAdd(&deg[dst[e]], w);
}

__global__ void dis_kernel(const float* __restrict__ deg, float* __restrict__ dis, int n) {
    int i = blockIdx.x * blockDim.x + threadIdx.x;
    if (i >= n) return;
    float d = deg[i];
    dis[i] = (d > 0.f) ? rsqrtf(fmaxf(d, 1e-12f)) : 0.f;
}

__global__ void bias_init_kernel(float* __restrict__ out, const float* __restrict__ b,
                                 int n, int C) {
    int idx = blockIdx.x * blockDim.x + threadIdx.x;
    if (idx >= n * C) return;
    out[idx] = b[idx % C];
}

// warp per edge; lanes cover channels (float4 granularity)
__global__ void scatter_kernel(const float* __restrict__ h, float* __restrict__ out,
                               const int* __restrict__ src, const int* __restrict__ dst,
                               const float* __restrict__ ew, const float* __restrict__ dis,
                               int C4) {
    int warp = (blockIdx.x * blockDim.x + threadIdx.x) >> 5;
    int lane = threadIdx.x & 31;
    if (warp >= ETOT) return;
    float w = ew[warp];
    if (w == 0.f) return;
    int s = src[warp], d = dst[warp];
    float nm = dis[s] * dis[d] * w;
    const float4* hs = (const float4*)(h + (size_t)s * (C4 * 4));
    float* o = out + (size_t)d * (C4 * 4);
    for (int c = lane; c < C4; c += 32) {
        float4 v = hs[c];
        atomicAdd(o + c * 4 + 0, v.x * nm);
        atomicAdd(o + c * 4 + 1, v.y * nm);
        atomicAdd(o + c * 4 + 2, v.z * nm);
        atomicAdd(o + c * 4 + 3, v.w * nm);
    }
}

// per-channel sum / sumsq over rows; grid = (C/256, rowSplits)
__global__ void bn_stats_kernel(const float* __restrict__ h,
                                float* __restrict__ sum, float* __restrict__ sumsq,
                                int n, int C) {
    int c = blockIdx.x * 256 + threadIdx.x;
    if (c >= C) return;
    int rowsPer = CEILDIV(n, gridDim.y);
    int r0 = blockIdx.y * rowsPer;
    int r1 = min(n, r0 + rowsPer);
    float s = 0.f, sq = 0.f;
    for (int r = r0; r < r1; r++) {
        float v = h[(size_t)r * C + c];
        s += v;
        sq += v * v;
    }
    atomicAdd(&sum[c], s);
    atomicAdd(&sumsq[c], sq);
}

__global__ void bn_apply_kernel(float* __restrict__ h,
                                const float* __restrict__ sum, const float* __restrict__ sumsq,
                                const float* __restrict__ gma, const float* __restrict__ bta,
                                int n, int C) {
    int idx = blockIdx.x * blockDim.x + threadIdx.x;
    if (idx >= n * C) return;
    int c = idx % C;
    float invn = 1.f / (float)n;
    float mean = sum[c] * invn;
    float var = sumsq[c] * invn - mean * mean;
    float y = (h[idx] - mean) * rsqrtf(var + 1e-5f) * gma[c] + bta[c];
    h[idx] = tanhf(y);
}

// per-node dot(h, rel_w) and dot(h, root_w); warp per node
__global__ void node_dots_kernel(const float* __restrict__ h,
                                 const float* __restrict__ relw,
                                 const float* __restrict__ rootw,
                                 const float* __restrict__ relb,
                                 float* __restrict__ t, float* __restrict__ score,
                                 int n, int C) {
    int node = (blockIdx.x * blockDim.x + threadIdx.x) >> 5;
    int lane = threadIdx.x & 31;
    if (node >= n) return;
    const float* hp = h + (size_t)node * C;
    float a = 0.f, b = 0.f;
    for (int c = lane; c < C; c += 32) {
        float v = hp[c];
        a += v * relw[c];
        b += v * rootw[c];
    }
#pragma unroll
    for (int o = 16; o > 0; o >>= 1) {
        a += __shfl_down_sync(0xffffffffu, a, o);
        b += __shfl_down_sync(0xffffffffu, b, o);
    }
    if (lane == 0) {
        t[node] = a;
        score[node] = b + relb[0];
    }
}

__global__ void score_edge_kernel(const int* __restrict__ src, const int* __restrict__ dst,
                                  const float* __restrict__ ew, const float* __restrict__ t,
                                  float* __restrict__ score) {
    int e = blockIdx.x * blockDim.x + threadIdx.x;
    if (e >= ETOT) return;
    float w = ew[e];
    if (w != 0.f) atomicAdd(&score[dst[e]], w * t[src[e]]);
}

__global__ void init_newid_kernel(int* __restrict__ newid, int n) {
    int i = blockIdx.x * blockDim.x + threadIdx.x;
    if (i < n) newid[i] = -1;
}

// Per-graph top-k via bitonic sort of (score desc, idx asc) — matches jax.lax.top_k order.
template <int SZ>
__global__ void __launch_bounds__(512)
topk_kernel(const float* __restrict__ score, int n_per, int ksel,
            int* __restrict__ perm, float* __restrict__ gain, int* __restrict__ newid) {
    __shared__ float sk[SZ];
    __shared__ int si[SZ];
    const int g = blockIdx.x;
    const int tid = threadIdx.x;
    for (int i = tid; i < SZ; i += 512) {
        if (i < n_per) { sk[i] = score[g * n_per + i]; si[i] = i; }
        else           { sk[i] = -INFINITY;            si[i] = 0x40000000 + i; }
    }
    __syncthreads();
    for (int kk = 2; kk <= SZ; kk <<= 1) {
        for (int j = kk >> 1; j > 0; j >>= 1) {
            for (int i = tid; i < SZ; i += 512) {
                int ixj = i ^ j;
                if (ixj > i) {
                    bool up = ((i & kk) == 0);
                    float s1 = sk[i], s2 = sk[ixj];
                    int i1 = si[i], i2 = si[ixj];
                    bool after = (s1 < s2) || (s1 == s2 && i1 > i2);
                    if (up == after) {
                        sk[i] = s2; sk[ixj] = s1;
                        si[i] = i2; si[ixj] = i1;
                    }
                }
            }
            __syncthreads();
        }
    }
    for (int r = tid; r < ksel; r += 512) {
        int old = g * n_per + si[r];
        int ng = g * ksel + r;
        perm[ng] = old;
        gain[ng] = tanhf(sk[r]);
        newid[old] = ng;
    }
}

__global__ void gather_kernel(const float* __restrict__ hin, float* __restrict__ hout,
                              const int* __restrict__ perm, const float* __restrict__ gain,
                              int rows, int C4) {
    int idx = blockIdx.x * blockDim.x + threadIdx.x;
    if (idx >= rows * C4) return;
    int row = idx / C4;
    int c = idx - row * C4;
    float gn = gain[row];
    float4 v = ((const float4*)hin)[(size_t)perm[row] * C4 + c];
    v.x *= gn; v.y *= gn; v.z *= gn; v.w *= gn;
    ((float4*)hout)[idx] = v;
}

__global__ void remap_kernel(int* __restrict__ src, int* __restrict__ dst,
                             float* __restrict__ ew, const int* __restrict__ newid) {
    int e = blockIdx.x * blockDim.x + threadIdx.x;
    if (e >= ETOT) return;
    int ns = newid[src[e]];
    int nd = newid[dst[e]];
    bool keep = (ns >= 0) && (nd >= 0);
    src[e] = keep ? ns : 0;
    dst[e] = keep ? nd : 0;
    ew[e] = keep ? ew[e] : 0.f;
}

__global__ void readout_kernel(const float* __restrict__ h, float* __restrict__ out) {
    int g = blockIdx.x;
    int c = threadIdx.x;  // 256 threads, C=256
    const float* p = h + (size_t)(g * K3) * 256 + c;
    float mx = -INFINITY, sm = 0.f;
    for (int i = 0; i < K3; i++) {
        float v = p[(size_t)i * 256];
        mx = fmaxf(mx, v);
        sm += v;
    }
    out[g * 512 + c] = mx;
    out[g * 512 + 256 + c] = sm / (float)K3;
}

// ---------------- host orchestration ----------------

extern "C" void kernel_launch(void* const* d_in, const int* in_sizes, int n_in,
                              void* d_out, int out_size) {
    const float* x    = (const float*)d_in[0];
    const int*   ei   = (const int*)d_in[1];
    const float* W1   = (const float*)d_in[2];
    const float* b1   = (const float*)d_in[3];
    const float* W2   = (const float*)d_in[4];
    const float* b2   = (const float*)d_in[5];
    const float* W3   = (const float*)d_in[6];
    const float* b3   = (const float*)d_in[7];
    const float* W4   = (const float*)d_in[8];
    const float* b4   = (const float*)d_in[9];
    const float* g1   = (const float*)d_in[10];
    const float* be1  = (const float*)d_in[11];
    const float* g2   = (const float*)d_in[12];
    const float* be2  = (const float*)d_in[13];
    const float* g3   = (const float*)d_in[14];
    const float* be3  = (const float*)d_in[15];
    const float* p1rw = (const float*)d_in[16];
    const float* p1rb = (const float*)d_in[17];
    const float* p1ow = (const float*)d_in[18];
    const float* p2rw = (const float*)d_in[19];
    const float* p2rb = (const float*)d_in[20];
    const float* p2ow = (const float*)d_in[21];
    const float* p3rw = (const float*)d_in[22];
    const float* p3rb = (const float*)d_in[23];
    const float* p3ow = (const float*)d_in[24];
    float* out = (float*)d_out;

    float *buf0, *buf1, *deg, *dis, *score, *t, *gain, *ew, *sum, *sumsq;
    int *src, *dst, *newid, *perm;
    cudaGetSymbolAddress((void**)&buf0, g_buf0);
    cudaGetSymbolAddress((void**)&buf1, g_buf1);
    cudaGetSymbolAddress((void**)&deg, g_deg);
    cudaGetSymbolAddress((void**)&dis, g_dis);
    cudaGetSymbolAddress((void**)&score, g_score);
    cudaGetSymbolAddress((void**)&t, g_t);
    cudaGetSymbolAddress((void**)&gain, g_gain);
    cudaGetSymbolAddress((void**)&ew, g_ew);
    cudaGetSymbolAddress((void**)&sum, g_sum);
    cudaGetSymbolAddress((void**)&sumsq, g_sumsq);
    cudaGetSymbolAddress((void**)&src, g_src);
    cudaGetSymbolAddress((void**)&dst, g_dst);
    cudaGetSymbolAddress((void**)&newid, g_newid);
    cudaGetSymbolAddress((void**)&perm, g_perm);

    const int EB = CEILDIV(ETOT, 256);                   // edge-parallel grid (blocks)
    const int SCATTER_BLOCKS = CEILDIV(ETOT * 32, 256);  // warp-per-edge: 32768 blocks

    edge_init_kernel<<<EB, 256>>>(ei, src, dst, ew);

    auto gcn = [&](const float* in, float* hbuf, float* aggbuf,
                   int n, int Cin, int Cout,
                   const float* W, const float* b) {
        gemm_kernel<<<dim3(Cout / BN, CEILDIV(n, BM)), 256>>>(in, W, hbuf, n, Cin, Cout);
        cudaMemsetAsync(deg, 0, (size_t)n * sizeof(float));
        deg_kernel<<<EB, 256>>>(dst, ew, deg);
        dis_kernel<<<CEILDIV(n, 256), 256>>>(deg, dis, n);
        bias_init_kernel<<<CEILDIV(n * Cout, 256), 256>>>(aggbuf, b, n, Cout);
        scatter_kernel<<<SCATTER_BLOCKS, 256>>>(hbuf, aggbuf, src, dst, ew, dis, Cout / 4);
    };
    auto bn_tanh = [&](float* hbuf, int n, int C, const float* gma, const float* bta) {
        cudaMemsetAsync(sum, 0, C * sizeof(float));
        cudaMemsetAsync(sumsq, 0, C * sizeof(float));
        bn_stats_kernel<<<dim3(CEILDIV(C, 256), 64), 256>>>(hbuf, sum, sumsq, n, C);
        bn_apply_kernel<<<CEILDIV(n * C, 256), 256>>>(hbuf, sum, sumsq, gma, bta, n, C);
    };
    auto pool_pre = [&](const float* hbuf, int n, int C,
                        const float* rw, const float* rb, const float* ow) {
        node_dots_kernel<<<CEILDIV(n * 32, 256), 256>>>(hbuf, rw, ow, rb, t, score, n, C);
        score_edge_kernel<<<EB, 256>>>(src, dst, ew, t, score);
        init_newid_kernel<<<CEILDIV(n, 256), 256>>>(newid, n);
    };
    auto pool_post = [&](const float* hbuf, float* outbuf, int ksel, int C) {
        int rows = BATCH * ksel;
        gather_kernel<<<CEILDIV(rows * (C / 4), 256), 256>>>(hbuf, outbuf, perm, gain,
                                                             rows, C / 4);
        remap_kernel<<<EB, 256>>>(src, dst, ew, newid);
    };

    // ---------- Layer 1 ----------
    gcn(x, buf1, buf0, N1, 512, 512, W1, b1);
    bn_tanh(buf0, N1, 512, g1, be1);
    pool_pre(buf0, N1, 512, p1rw, p1rb, p1ow);
    topk_kernel<1024><<<BATCH, 512>>>(score, 1024, K1, perm, gain, newid);
    pool_post(buf0, buf1, K1, 512);

    // ---------- Layer 2 ----------
    gcn(buf1, buf0, buf1, N2, 512, 512, W2, b2);
    bn_tanh(buf1, N2, 512, g2, be2);
    pool_pre(buf1, N2, 512, p2rw, p2rb, p2ow);
    topk_kernel<1024><<<BATCH, 512>>>(score, K1, K2, perm, gain, newid);
    pool_post(buf1, buf0, K2, 512);

    // ---------- Layer 3 ----------
    gcn(buf0, buf1, buf0, N3, 512, 256, W3, b3);
    bn_tanh(buf0, N3, 256, g3, be3);
    pool_pre(buf0, N3, 256, p3rw, p3rb, p3ow);
    topk_kernel<512><<<BATCH, 512>>>(score, K2, K3, perm, gain, newid);
    pool_post(buf0, buf1, K3, 256);

    // ---------- Layer 4 (no BN / pool) ----------
    gcn(buf1, buf0, buf1, N4, 256, 256, W4, b4);

    // ---------- readout ----------
    readout_kernel<<<BATCH, 256>>>(buf1, out);
    (void)in_sizes; (void)n_in; (void)out_size;
}

// round 5
// speedup vs baseline: 1.2506x; 1.2004x over previous
#include <cuda_runtime.h>
#include <math.h>

// ---------------- problem constants ----------------
#define BATCH   32
#define ETOT    262144          // 32*1024*8 edges (fixed; masked via ew)
#define NMAX    32768           // max nodes (layer 1)
#define K1      615             // ceil(0.6*1024)
#define K2      369             // ceil(0.6*615)
#define K3      185             // ceil(0.5*369)
#define N1      32768
#define N2      (BATCH*K1)      // 19680
#define N3      (BATCH*K2)      // 11808
#define N4      (BATCH*K3)      // 5920

#define CEILDIV(a,b) (((a)+(b)-1)/(b))

// ---------------- static device scratch (no allocs allowed) ----------------
__device__ float g_buf0[(size_t)NMAX * 512];
__device__ float g_buf1[(size_t)NMAX * 512];
__device__ float g_dis[NMAX];
__device__ float g_score[NMAX];
__device__ float g_t[NMAX];
__device__ float g_gain[NMAX];
__device__ int   g_newid[NMAX];
__device__ int   g_perm[NMAX];
__device__ int   g_src[ETOT];
__device__ int   g_dst[ETOT];
__device__ float g_ew[ETOT];
__device__ float g_sum[512];
__device__ float g_sumsq[512];
// CSR scratch
__device__ int   g_icount[NMAX];
__device__ int   g_rowptr[NMAX + 1];
__device__ int   g_cursor[NMAX];
__device__ int   g_esrc[ETOT];
__device__ float g_enorm[ETOT];

// ---------------- kernels ----------------

__global__ void edge_init_kernel(const int* __restrict__ ei,
                                 int* __restrict__ src, int* __restrict__ dst,
                                 float* __restrict__ ew) {
    int e = blockIdx.x * blockDim.x + threadIdx.x;
    if (e >= ETOT) return;
    src[e] = ei[e];
    dst[e] = ei[ETOT + e];
    ew[e]  = 1.0f;
}

// ---------------------------------------------------------------
// Double-buffered 128x128x16 register-tiled SGEMM.
// ---------------------------------------------------------------
#define BM 128
#define BN 128
#define BK 16
#define TM 8
#define TN 8
#define BMP 132

__global__ void __launch_bounds__(256)
gemm_kernel(const float* __restrict__ A, const float* __restrict__ B,
            float* __restrict__ C, int M, int K, int N) {
    __shared__ float As[2][BK][BMP];
    __shared__ float Bs[2][BK][BN];

    const int tid = threadIdx.x;
    const int tx = tid & 15;
    const int ty = tid >> 4;
    const int mBase = blockIdx.y * BM;
    const int nBase = blockIdx.x * BN;

    const int ar0 = tid >> 2,         ac0 = (tid & 3) * 4;
    const int ar1 = (tid + 256) >> 2, ac1 = ((tid + 256) & 3) * 4;
    const int br0 = tid >> 5,         bc0 = (tid & 31) * 4;
    const int br1 = (tid + 256) >> 5, bc1 = ((tid + 256) & 31) * 4;

    float acc[TM][TN];
#pragma unroll
    for (int i = 0; i < TM; i++)
#pragma unroll
        for (int j = 0; j < TN; j++) acc[i][j] = 0.f;

    const float4 z4 = make_float4(0.f, 0.f, 0.f, 0.f);

    {
        int gm0 = mBase + ar0, gm1 = mBase + ar1;
        float4 a0 = (gm0 < M) ? *(const float4*)(A + (size_t)gm0 * K + ac0) : z4;
        float4 a1 = (gm1 < M) ? *(const float4*)(A + (size_t)gm1 * K + ac1) : z4;
        float4 b0 = *(const float4*)(B + (size_t)br0 * N + nBase + bc0);
        float4 b1 = *(const float4*)(B + (size_t)br1 * N + nBase + bc1);
        As[0][ac0 + 0][ar0] = a0.x; As[0][ac0 + 1][ar0] = a0.y;
        As[0][ac0 + 2][ar0] = a0.z; As[0][ac0 + 3][ar0] = a0.w;
        As[0][ac1 + 0][ar1] = a1.x; As[0][ac1 + 1][ar1] = a1.y;
        As[0][ac1 + 2][ar1] = a1.z; As[0][ac1 + 3][ar1] = a1.w;
        *(float4*)&Bs[0][br0][bc0] = b0;
        *(float4*)&Bs[0][br1][bc1] = b1;
    }
    __syncthreads();

    int buf = 0;
    for (int k0 = 0; k0 < K; k0 += BK, buf ^= 1) {
        const int kn = k0 + BK;
        const bool hasNext = kn < K;
        float4 sa0, sa1, sb0, sb1;
        if (hasNext) {
            int gm0 = mBase + ar0, gm1 = mBase + ar1;
            sa0 = (gm0 < M) ? *(const float4*)(A + (size_t)gm0 * K + kn + ac0) : z4;
            sa1 = (gm1 < M) ? *(const float4*)(A + (size_t)gm1 * K + kn + ac1) : z4;
            sb0 = *(const float4*)(B + (size_t)(kn + br0) * N + nBase + bc0);
            sb1 = *(const float4*)(B + (size_t)(kn + br1) * N + nBase + bc1);
        }
#pragma unroll
        for (int kk = 0; kk < BK; kk++) {
            float4 a0 = *(const float4*)&As[buf][kk][ty * TM];
            float4 a1 = *(const float4*)&As[buf][kk][ty * TM + 4];
            float4 b0 = *(const float4*)&Bs[buf][kk][tx * TN];
            float4 b1 = *(const float4*)&Bs[buf][kk][tx * TN + 4];
            float a[TM] = {a0.x, a0.y, a0.z, a0.w, a1.x, a1.y, a1.z, a1.w};
            float b[TN] = {b0.x, b0.y, b0.z, b0.w, b1.x, b1.y, b1.z, b1.w};
#pragma unroll
            for (int i = 0; i < TM; i++)
#pragma unroll
                for (int j = 0; j < TN; j++) acc[i][j] += a[i] * b[j];
        }
        if (hasNext) {
            int nb = buf ^ 1;
            As[nb][ac0 + 0][ar0] = sa0.x; As[nb][ac0 + 1][ar0] = sa0.y;
            As[nb][ac0 + 2][ar0] = sa0.z; As[nb][ac0 + 3][ar0] = sa0.w;
            As[nb][ac1 + 0][ar1] = sa1.x; As[nb][ac1 + 1][ar1] = sa1.y;
            As[nb][ac1 + 2][ar1] = sa1.z; As[nb][ac1 + 3][ar1] = sa1.w;
            *(float4*)&Bs[nb][br0][bc0] = sb0;
            *(float4*)&Bs[nb][br1][bc1] = sb1;
            __syncthreads();
        }
    }

#pragma unroll
    for (int i = 0; i < TM; i++) {
        int row = mBase + ty * TM + i;
        if (row < M) {
            float* cp = C + (size_t)row * N + nBase + tx * TN;
            *(float4*)(cp)     = make_float4(acc[i][0], acc[i][1], acc[i][2], acc[i][3]);
            *(float4*)(cp + 4) = make_float4(acc[i][4], acc[i][5], acc[i][6], acc[i][7]);
        }
    }
}

// ---------------- CSR build ----------------

__global__ void count_kernel(const int* __restrict__ dst, const float* __restrict__ ew,
                             int* __restrict__ cnt) {
    int e = blockIdx.x * blockDim.x + threadIdx.x;
    if (e >= ETOT) return;
    if (ew[e] != 0.f) atomicAdd(&cnt[dst[e]], 1);
}

// single block, 1024 threads: exclusive scan of cnt -> rowptr & cursor, dis = rsqrt(cnt)
__global__ void __launch_bounds__(1024)
scan_kernel(const int* __restrict__ cnt, int* __restrict__ rowptr,
            int* __restrict__ cursor, float* __restrict__ dis, int n) {
    __shared__ int warpsum[32];
    const int tid = threadIdx.x;
    const int chunk = CEILDIV(n, 1024);
    const int begin = tid * chunk;
    const int end = min(n, begin + chunk);
    int s = 0;
    for (int i = begin; i < end; i++) s += cnt[i];

    const int lane = tid & 31, wid = tid >> 5;
    int v = s;
#pragma unroll
    for (int off = 1; off < 32; off <<= 1) {
        int u = __shfl_up_sync(0xffffffffu, v, off);
        if (lane >= off) v += u;
    }
    if (lane == 31) warpsum[wid] = v;
    __syncthreads();
    if (wid == 0) {
        int w = warpsum[lane];
#pragma unroll
        for (int off = 1; off < 32; off <<= 1) {
            int u = __shfl_up_sync(0xffffffffu, w, off);
            if (lane >= off) w += u;
        }
        warpsum[lane] = w;
    }
    __syncthreads();
    int excl = v - s + (wid > 0 ? warpsum[wid - 1] : 0);

    int run = excl;
    for (int i = begin; i < end; i++) {
        rowptr[i] = run;
        cursor[i] = run;
        int c = cnt[i];
        dis[i] = (c > 0) ? rsqrtf((float)c) : 0.f;
        run += c;
    }
    if (end == n) rowptr[n] = run;
}

__global__ void fill_kernel(const int* __restrict__ src, const int* __restrict__ dst,
                            const float* __restrict__ ew, const float* __restrict__ dis,
                            int* __restrict__ cursor,
                            int* __restrict__ esrc, float* __restrict__ enorm) {
    int e = blockIdx.x * blockDim.x + threadIdx.x;
    if (e >= ETOT) return;
    float w = ew[e];
    if (w == 0.f) return;
    int s = src[e], d = dst[e];
    int pos = atomicAdd(&cursor[d], 1);
    esrc[pos] = s;
    enorm[pos] = dis[s] * dis[d] * w;
}

// one block per node, C/4 threads; each thread owns one float4 column slice.
template <int C>
__global__ void gather_agg_kernel(const float* __restrict__ h,
                                  const int* __restrict__ rowptr,
                                  const int* __restrict__ esrc,
                                  const float* __restrict__ enorm,
                                  const float* __restrict__ bias,
                                  float* __restrict__ out) {
    const int node = blockIdx.x;
    const int tid = threadIdx.x;           // 0 .. C/4-1
    float4 acc = *(const float4*)(bias + tid * 4);
    int b = rowptr[node];
    const int e = rowptr[node + 1];
    for (; b + 1 < e; b += 2) {
        int s0 = esrc[b],     s1 = esrc[b + 1];
        float n0 = enorm[b],  n1 = enorm[b + 1];
        float4 v0 = *(const float4*)(h + (size_t)s0 * C + tid * 4);
        float4 v1 = *(const float4*)(h + (size_t)s1 * C + tid * 4);
        acc.x += v0.x * n0; acc.y += v0.y * n0; acc.z += v0.z * n0; acc.w += v0.w * n0;
        acc.x += v1.x * n1; acc.y += v1.y * n1; acc.z += v1.z * n1; acc.w += v1.w * n1;
    }
    if (b < e) {
        int s0 = esrc[b];
        float n0 = enorm[b];
        float4 v0 = *(const float4*)(h + (size_t)s0 * C + tid * 4);
        acc.x += v0.x * n0; acc.y += v0.y * n0; acc.z += v0.z * n0; acc.w += v0.w * n0;
    }
    *(float4*)(out + (size_t)node * C + tid * 4) = acc;
}

// ---------------- BN / pool / misc ----------------

__global__ void bn_stats_kernel(const float* __restrict__ h,
                                float* __restrict__ sum, float* __restrict__ sumsq,
                                int n, int C) {
    int c = blockIdx.x * 256 + threadIdx.x;
    if (c >= C) return;
    int rowsPer = CEILDIV(n, gridDim.y);
    int r0 = blockIdx.y * rowsPer;
    int r1 = min(n, r0 + rowsPer);
    float s = 0.f, sq = 0.f;
    for (int r = r0; r < r1; r++) {
        float v = h[(size_t)r * C + c];
        s += v;
        sq += v * v;
    }
    atomicAdd(&sum[c], s);
    atomicAdd(&sumsq[c], sq);
}

__global__ void bn_apply_kernel(float* __restrict__ h,
                                const float* __restrict__ sum, const float* __restrict__ sumsq,
                                const float* __restrict__ gma, const float* __restrict__ bta,
                                int n, int C) {
    int idx = blockIdx.x * blockDim.x + threadIdx.x;
    if (idx >= n * C) return;
    int c = idx % C;
    float invn = 1.f / (float)n;
    float mean = sum[c] * invn;
    float var = sumsq[c] * invn - mean * mean;
    float y = (h[idx] - mean) * rsqrtf(var + 1e-5f) * gma[c] + bta[c];
    h[idx] = tanhf(y);
}

__global__ void node_dots_kernel(const float* __restrict__ h,
                                 const float* __restrict__ relw,
                                 const float* __restrict__ rootw,
                                 const float* __restrict__ relb,
                                 float* __restrict__ t, float* __restrict__ score,
                                 int n, int C) {
    int node = (blockIdx.x * blockDim.x + threadIdx.x) >> 5;
    int lane = threadIdx.x & 31;
    if (node >= n) return;
    const float* hp = h + (size_t)node * C;
    float a = 0.f, b = 0.f;
    for (int c = lane; c < C; c += 32) {
        float v = hp[c];
        a += v * relw[c];
        b += v * rootw[c];
    }
#pragma unroll
    for (int o = 16; o > 0; o >>= 1) {
        a += __shfl_down_sync(0xffffffffu, a, o);
        b += __shfl_down_sync(0xffffffffu, b, o);
    }
    if (lane == 0) {
        t[node] = a;
        score[node] = b + relb[0];
    }
}

__global__ void score_edge_kernel(const int* __restrict__ src, const int* __restrict__ dst,
                                  const float* __restrict__ ew, const float* __restrict__ t,
                                  float* __restrict__ score) {
    int e = blockIdx.x * blockDim.x + threadIdx.x;
    if (e >= ETOT) return;
    float w = ew[e];
    if (w != 0.f) atomicAdd(&score[dst[e]], w * t[src[e]]);
}

__global__ void init_newid_kernel(int* __restrict__ newid, int n) {
    int i = blockIdx.x * blockDim.x + threadIdx.x;
    if (i < n) newid[i] = -1;
}

template <int SZ>
__global__ void __launch_bounds__(512)
topk_kernel(const float* __restrict__ score, int n_per, int ksel,
            int* __restrict__ perm, float* __restrict__ gain, int* __restrict__ newid) {
    __shared__ float sk[SZ];
    __shared__ int si[SZ];
    const int g = blockIdx.x;
    const int tid = threadIdx.x;
    for (int i = tid; i < SZ; i += 512) {
        if (i < n_per) { sk[i] = score[g * n_per + i]; si[i] = i; }
        else           { sk[i] = -INFINITY;            si[i] = 0x40000000 + i; }
    }
    __syncthreads();
    for (int kk = 2; kk <= SZ; kk <<= 1) {
        for (int j = kk >> 1; j > 0; j >>= 1) {
            for (int i = tid; i < SZ; i += 512) {
                int ixj = i ^ j;
                if (ixj > i) {
                    bool up = ((i & kk) == 0);
                    float s1 = sk[i], s2 = sk[ixj];
                    int i1 = si[i], i2 = si[ixj];
                    bool after = (s1 < s2) || (s1 == s2 && i1 > i2);
                    if (up == after) {
                        sk[i] = s2; sk[ixj] = s1;
                        si[i] = i2; si[ixj] = i1;
                    }
                }
            }
            __syncthreads();
        }
    }
    for (int r = tid; r < ksel; r += 512) {
        int old = g * n_per + si[r];
        int ng = g * ksel + r;
        perm[ng] = old;
        gain[ng] = tanhf(sk[r]);
        newid[old] = ng;
    }
}

__global__ void gather_kernel(const float* __restrict__ hin, float* __restrict__ hout,
                              const int* __restrict__ perm, const float* __restrict__ gain,
                              int rows, int C4) {
    int idx = blockIdx.x * blockDim.x + threadIdx.x;
    if (idx >= rows * C4) return;
    int row = idx / C4;
    int c = idx - row * C4;
    float gn = gain[row];
    float4 v = ((const float4*)hin)[(size_t)perm[row] * C4 + c];
    v.x *= gn; v.y *= gn; v.z *= gn; v.w *= gn;
    ((float4*)hout)[idx] = v;
}

__global__ void remap_kernel(int* __restrict__ src, int* __restrict__ dst,
                             float* __restrict__ ew, const int* __restrict__ newid) {
    int e = blockIdx.x * blockDim.x + threadIdx.x;
    if (e >= ETOT) return;
    int ns = newid[src[e]];
    int nd = newid[dst[e]];
    bool keep = (ns >= 0) && (nd >= 0);
    src[e] = keep ? ns : 0;
    dst[e] = keep ? nd : 0;
    ew[e] = keep ? ew[e] : 0.f;
}

__global__ void readout_kernel(const float* __restrict__ h, float* __restrict__ out) {
    int g = blockIdx.x;
    int c = threadIdx.x;  // 256 threads, C=256
    const float* p = h + (size_t)(g * K3) * 256 + c;
    float mx = -INFINITY, sm = 0.f;
    for (int i = 0; i < K3; i++) {
        float v = p[(size_t)i * 256];
        mx = fmaxf(mx, v);
        sm += v;
    }
    out[g * 512 + c] = mx;
    out[g * 512 + 256 + c] = sm / (float)K3;
}

// ---------------- host orchestration ----------------

extern "C" void kernel_launch(void* const* d_in, const int* in_sizes, int n_in,
                              void* d_out, int out_size) {
    const float* x    = (const float*)d_in[0];
    const int*   ei   = (const int*)d_in[1];
    const float* W1   = (const float*)d_in[2];
    const float* b1   = (const float*)d_in[3];
    const float* W2   = (const float*)d_in[4];
    const float* b2   = (const float*)d_in[5];
    const float* W3   = (const float*)d_in[6];
    const float* b3   = (const float*)d_in[7];
    const float* W4   = (const float*)d_in[8];
    const float* b4   = (const float*)d_in[9];
    const float* g1   = (const float*)d_in[10];
    const float* be1  = (const float*)d_in[11];
    const float* g2   = (const float*)d_in[12];
    const float* be2  = (const float*)d_in[13];
    const float* g3   = (const float*)d_in[14];
    const float* be3  = (const float*)d_in[15];
    const float* p1rw = (const float*)d_in[16];
    const float* p1rb = (const float*)d_in[17];
    const float* p1ow = (const float*)d_in[18];
    const float* p2rw = (const float*)d_in[19];
    const float* p2rb = (const float*)d_in[20];
    const float* p2ow = (const float*)d_in[21];
    const float* p3rw = (const float*)d_in[22];
    const float* p3rb = (const float*)d_in[23];
    const float* p3ow = (const float*)d_in[24];
    float* out = (float*)d_out;

    float *buf0, *buf1, *dis, *score, *t, *gain, *ew, *sum, *sumsq, *enorm;
    int *src, *dst, *newid, *perm, *icount, *rowptr, *cursor, *esrc;
    cudaGetSymbolAddress((void**)&buf0, g_buf0);
    cudaGetSymbolAddress((void**)&buf1, g_buf1);
    cudaGetSymbolAddress((void**)&dis, g_dis);
    cudaGetSymbolAddress((void**)&score, g_score);
    cudaGetSymbolAddress((void**)&t, g_t);
    cudaGetSymbolAddress((void**)&gain, g_gain);
    cudaGetSymbolAddress((void**)&ew, g_ew);
    cudaGetSymbolAddress((void**)&sum, g_sum);
    cudaGetSymbolAddress((void**)&sumsq, g_sumsq);
    cudaGetSymbolAddress((void**)&src, g_src);
    cudaGetSymbolAddress((void**)&dst, g_dst);
    cudaGetSymbolAddress((void**)&newid, g_newid);
    cudaGetSymbolAddress((void**)&perm, g_perm);
    cudaGetSymbolAddress((void**)&icount, g_icount);
    cudaGetSymbolAddress((void**)&rowptr, g_rowptr);
    cudaGetSymbolAddress((void**)&cursor, g_cursor);
    cudaGetSymbolAddress((void**)&esrc, g_esrc);
    cudaGetSymbolAddress((void**)&enorm, g_enorm);

    const int EB = CEILDIV(ETOT, 256);

    edge_init_kernel<<<EB, 256>>>(ei, src, dst, ew);

    auto gcn = [&](const float* in, float* hbuf, float* aggbuf,
                   int n, int Cin, int Cout,
                   const float* W, const float* b) {
        gemm_kernel<<<dim3(Cout / BN, CEILDIV(n, BM)), 256>>>(in, W, hbuf, n, Cin, Cout);
        cudaMemsetAsync(icount, 0, (size_t)n * sizeof(int));
        count_kernel<<<EB, 256>>>(dst, ew, icount);
        scan_kernel<<<1, 1024>>>(icount, rowptr, cursor, dis, n);
        fill_kernel<<<EB, 256>>>(src, dst, ew, dis, cursor, esrc, enorm);
        if (Cout == 512)
            gather_agg_kernel<512><<<n, 128>>>(hbuf, rowptr, esrc, enorm, b, aggbuf);
        else
            gather_agg_kernel<256><<<n, 64>>>(hbuf, rowptr, esrc, enorm, b, aggbuf);
    };
    auto bn_tanh = [&](float* hbuf, int n, int C, const float* gma, const float* bta) {
        cudaMemsetAsync(sum, 0, C * sizeof(float));
        cudaMemsetAsync(sumsq, 0, C * sizeof(float));
        bn_stats_kernel<<<dim3(CEILDIV(C, 256), 64), 256>>>(hbuf, sum, sumsq, n, C);
        bn_apply_kernel<<<CEILDIV(n * C, 256), 256>>>(hbuf, sum, sumsq, gma, bta, n, C);
    };
    auto pool_pre = [&](const float* hbuf, int n, int C,
                        const float* rw, const float* rb, const float* ow) {
        node_dots_kernel<<<CEILDIV(n * 32, 256), 256>>>(hbuf, rw, ow, rb, t, score, n, C);
        score_edge_kernel<<<EB, 256>>>(src, dst, ew, t, score);
        init_newid_kernel<<<CEILDIV(n, 256), 256>>>(newid, n);
    };
    auto pool_post = [&](const float* hbuf, float* outbuf, int ksel, int C) {
        int rows = BATCH * ksel;
        gather_kernel<<<CEILDIV(rows * (C / 4), 256), 256>>>(hbuf, outbuf, perm, gain,
                                                             rows, C / 4);
        remap_kernel<<<EB, 256>>>(src, dst, ew, newid);
    };

    // ---------- Layer 1 ----------
    gcn(x, buf1, buf0, N1, 512, 512, W1, b1);
    bn_tanh(buf0, N1, 512, g1, be1);
    pool_pre(buf0, N1, 512, p1rw, p1rb, p1ow);
    topk_kernel<1024><<<BATCH, 512>>>(score, 1024, K1, perm, gain, newid);
    pool_post(buf0, buf1, K1, 512);

    // ---------- Layer 2 ----------
    gcn(buf1, buf0, buf1, N2, 512, 512, W2, b2);
    bn_tanh(buf1, N2, 512, g2, be2);
    pool_pre(buf1, N2, 512, p2rw, p2rb, p2ow);
    topk_kernel<1024><<<BATCH, 512>>>(score, K1, K2, perm, gain, newid);
    pool_post(buf1, buf0, K2, 512);

    // ---------- Layer 3 ----------
    gcn(buf0, buf1, buf0, N3, 512, 256, W3, b3);
    bn_tanh(buf0, N3, 256, g3, be3);
    pool_pre(buf0, N3, 256, p3rw, p3rb, p3ow);
    topk_kernel<512><<<BATCH, 512>>>(score, K2, K3, perm, gain, newid);
    pool_post(buf0, buf1, K3, 256);

    // ---------- Layer 4 (no BN / pool) ----------
    gcn(buf1, buf0, buf1, N4, 256, 256, W4, b4);

    // ---------- readout ----------
    readout_kernel<<<BATCH, 256>>>(buf1, out);
    (void)in_sizes; (void)n_in; (void)out_size;
}

// round 6
// speedup vs baseline: 1.3758x; 1.1001x over previous
#include <cuda_runtime.h>
#include <math.h>

// ---------------- problem constants ----------------
#define BATCH   32
#define ETOT    262144
#define NMAX    32768
#define K1      615
#define K2      369
#define K3      185
#define N1      32768
#define N2      (BATCH*K1)      // 19680
#define N3      (BATCH*K2)      // 11808
#define N4      (BATCH*K3)      // 5920

#define CEILDIV(a,b) (((a)+(b)-1)/(b))

// ---------------- static device scratch ----------------
__device__ float g_buf0[(size_t)NMAX * 512];
__device__ float g_buf1[(size_t)NMAX * 512];
__device__ float g_dis[NMAX];
__device__ float g_score[NMAX];
__device__ float g_t[NMAX];
__device__ float g_gain[NMAX];
__device__ int   g_newid[NMAX];
__device__ int   g_perm[NMAX];
__device__ int   g_src[ETOT];
__device__ int   g_dst[ETOT];
__device__ float g_ew[ETOT];
__device__ float g_sum[512];
__device__ float g_sumsq[512];
// CSR scratch
__device__ int   g_icount[NMAX];
__device__ int   g_rowptr[NMAX + 1];
__device__ int   g_cursor[NMAX];
__device__ int   g_esrc[ETOT];
__device__ float g_enorm[ETOT];
__device__ int   g_blocksum[32];
__device__ int   g_blockoff[32];

// ---------------- kernels ----------------

__global__ void edge_init_kernel(const int* __restrict__ ei,
                                 int* __restrict__ src, int* __restrict__ dst,
                                 float* __restrict__ ew) {
    int e = blockIdx.x * blockDim.x + threadIdx.x;
    if (e >= ETOT) return;
    src[e] = ei[e];
    dst[e] = ei[ETOT + e];
    ew[e]  = 1.0f;
}

// ---------------------------------------------------------------
// Double-buffered 128x128x16 register-tiled SGEMM.
// ---------------------------------------------------------------
#define BM 128
#define BN 128
#define BK 16
#define TM 8
#define TN 8
#define BMP 132

__global__ void __launch_bounds__(256)
gemm_kernel(const float* __restrict__ A, const float* __restrict__ B,
            float* __restrict__ C, int M, int K, int N) {
    __shared__ float As[2][BK][BMP];
    __shared__ float Bs[2][BK][BN];

    const int tid = threadIdx.x;
    const int tx = tid & 15;
    const int ty = tid >> 4;
    const int mBase = blockIdx.y * BM;
    const int nBase = blockIdx.x * BN;

    const int ar0 = tid >> 2,         ac0 = (tid & 3) * 4;
    const int ar1 = (tid + 256) >> 2, ac1 = ((tid + 256) & 3) * 4;
    const int br0 = tid >> 5,         bc0 = (tid & 31) * 4;
    const int br1 = (tid + 256) >> 5, bc1 = ((tid + 256) & 31) * 4;

    float acc[TM][TN];
#pragma unroll
    for (int i = 0; i < TM; i++)
#pragma unroll
        for (int j = 0; j < TN; j++) acc[i][j] = 0.f;

    const float4 z4 = make_float4(0.f, 0.f, 0.f, 0.f);

    {
        int gm0 = mBase + ar0, gm1 = mBase + ar1;
        float4 a0 = (gm0 < M) ? *(const float4*)(A + (size_t)gm0 * K + ac0) : z4;
        float4 a1 = (gm1 < M) ? *(const float4*)(A + (size_t)gm1 * K + ac1) : z4;
        float4 b0 = *(const float4*)(B + (size_t)br0 * N + nBase + bc0);
        float4 b1 = *(const float4*)(B + (size_t)br1 * N + nBase + bc1);
        As[0][ac0 + 0][ar0] = a0.x; As[0][ac0 + 1][ar0] = a0.y;
        As[0][ac0 + 2][ar0] = a0.z; As[0][ac0 + 3][ar0] = a0.w;
        As[0][ac1 + 0][ar1] = a1.x; As[0][ac1 + 1][ar1] = a1.y;
        As[0][ac1 + 2][ar1] = a1.z; As[0][ac1 + 3][ar1] = a1.w;
        *(float4*)&Bs[0][br0][bc0] = b0;
        *(float4*)&Bs[0][br1][bc1] = b1;
    }
    __syncthreads();

    int buf = 0;
    for (int k0 = 0; k0 < K; k0 += BK, buf ^= 1) {
        const int kn = k0 + BK;
        const bool hasNext = kn < K;
        float4 sa0, sa1, sb0, sb1;
        if (hasNext) {
            int gm0 = mBase + ar0, gm1 = mBase + ar1;
            sa0 = (gm0 < M) ? *(const float4*)(A + (size_t)gm0 * K + kn + ac0) : z4;
            sa1 = (gm1 < M) ? *(const float4*)(A + (size_t)gm1 * K + kn + ac1) : z4;
            sb0 = *(const float4*)(B + (size_t)(kn + br0) * N + nBase + bc0);
            sb1 = *(const float4*)(B + (size_t)(kn + br1) * N + nBase + bc1);
        }
#pragma unroll
        for (int kk = 0; kk < BK; kk++) {
            float4 a0 = *(const float4*)&As[buf][kk][ty * TM];
            float4 a1 = *(const float4*)&As[buf][kk][ty * TM + 4];
            float4 b0 = *(const float4*)&Bs[buf][kk][tx * TN];
            float4 b1 = *(const float4*)&Bs[buf][kk][tx * TN + 4];
            float a[TM] = {a0.x, a0.y, a0.z, a0.w, a1.x, a1.y, a1.z, a1.w};
            float b[TN] = {b0.x, b0.y, b0.z, b0.w, b1.x, b1.y, b1.z, b1.w};
#pragma unroll
            for (int i = 0; i < TM; i++)
#pragma unroll
                for (int j = 0; j < TN; j++) acc[i][j] += a[i] * b[j];
        }
        if (hasNext) {
            int nb = buf ^ 1;
            As[nb][ac0 + 0][ar0] = sa0.x; As[nb][ac0 + 1][ar0] = sa0.y;
            As[nb][ac0 + 2][ar0] = sa0.z; As[nb][ac0 + 3][ar0] = sa0.w;
            As[nb][ac1 + 0][ar1] = sa1.x; As[nb][ac1 + 1][ar1] = sa1.y;
            As[nb][ac1 + 2][ar1] = sa1.z; As[nb][ac1 + 3][ar1] = sa1.w;
            *(float4*)&Bs[nb][br0][bc0] = sb0;
            *(float4*)&Bs[nb][br1][bc1] = sb1;
            __syncthreads();
        }
    }

#pragma unroll
    for (int i = 0; i < TM; i++) {
        int row = mBase + ty * TM + i;
        if (row < M) {
            float* cp = C + (size_t)row * N + nBase + tx * TN;
            *(float4*)(cp)     = make_float4(acc[i][0], acc[i][1], acc[i][2], acc[i][3]);
            *(float4*)(cp + 4) = make_float4(acc[i][4], acc[i][5], acc[i][6], acc[i][7]);
        }
    }
}

// ---------------- CSR build ----------------

__global__ void count_kernel(const int* __restrict__ dst, const float* __restrict__ ew,
                             int* __restrict__ cnt) {
    int e = blockIdx.x * blockDim.x + threadIdx.x;
    if (e >= ETOT) return;
    if (ew[e] != 0.f) atomicAdd(&cnt[dst[e]], 1);
}

// phase 1: per-block (1024 elems) exclusive scan, coalesced.
__global__ void __launch_bounds__(1024)
scan_partial_kernel(const int* __restrict__ cnt, int* __restrict__ rowptr,
                    int* __restrict__ blocksum, int n) {
    __shared__ int warpsum[32];
    const int tid = threadIdx.x;
    const int i = blockIdx.x * 1024 + tid;
    int v = (i < n) ? cnt[i] : 0;
    const int s = v;

    const int lane = tid & 31, wid = tid >> 5;
#pragma unroll
    for (int off = 1; off < 32; off <<= 1) {
        int u = __shfl_up_sync(0xffffffffu, v, off);
        if (lane >= off) v += u;
    }
    if (lane == 31) warpsum[wid] = v;
    __syncthreads();
    if (wid == 0) {
        int w = warpsum[lane];
#pragma unroll
        for (int off = 1; off < 32; off <<= 1) {
            int u = __shfl_up_sync(0xffffffffu, w, off);
            if (lane >= off) w += u;
        }
        warpsum[lane] = w;
    }
    __syncthreads();
    int excl = v - s + (wid > 0 ? warpsum[wid - 1] : 0);
    if (i < n) rowptr[i] = excl;
    if (tid == 1023) blocksum[blockIdx.x] = excl + s;
}

// phase 2: scan <=32 block sums with one warp; write rowptr[n] = total.
__global__ void scan_blocksums_kernel(const int* __restrict__ blocksum,
                                      int* __restrict__ blockoff,
                                      int* __restrict__ rowptr,
                                      int nblocks, int n) {
    const int lane = threadIdx.x;
    int v = (lane < nblocks) ? blocksum[lane] : 0;
    const int s = v;
#pragma unroll
    for (int off = 1; off < 32; off <<= 1) {
        int u = __shfl_up_sync(0xffffffffu, v, off);
        if (lane >= off) v += u;
    }
    if (lane < nblocks) blockoff[lane] = v - s;
    if (lane == 31) rowptr[n] = v;
}

// phase 3: add block offsets, emit cursor & dis.
__global__ void __launch_bounds__(1024)
scan_finalize_kernel(const int* __restrict__ cnt, int* __restrict__ rowptr,
                     const int* __restrict__ blockoff,
                     int* __restrict__ cursor, float* __restrict__ dis, int n) {
    const int i = blockIdx.x * 1024 + threadIdx.x;
    if (i >= n) return;
    int r = rowptr[i] + blockoff[blockIdx.x];
    rowptr[i] = r;
    cursor[i] = r;
    int c = cnt[i];
    dis[i] = (c > 0) ? rsqrtf((float)c) : 0.f;
}

__global__ void fill_kernel(const int* __restrict__ src, const int* __restrict__ dst,
                            const float* __restrict__ ew, const float* __restrict__ dis,
                            int* __restrict__ cursor,
                            int* __restrict__ esrc, float* __restrict__ enorm) {
    int e = blockIdx.x * blockDim.x + threadIdx.x;
    if (e >= ETOT) return;
    float w = ew[e];
    if (w == 0.f) return;
    int s = src[e], d = dst[e];
    int pos = atomicAdd(&cursor[d], 1);
    esrc[pos] = s;
    enorm[pos] = dis[s] * dis[d] * w;
}

// one block per node, C/4 threads; each thread owns one float4 column slice.
template <int C>
__global__ void gather_agg_kernel(const float* __restrict__ h,
                                  const int* __restrict__ rowptr,
                                  const int* __restrict__ esrc,
                                  const float* __restrict__ enorm,
                                  const float* __restrict__ bias,
                                  float* __restrict__ out) {
    const int node = blockIdx.x;
    const int tid = threadIdx.x;
    float4 acc = *(const float4*)(bias + tid * 4);
    int b = rowptr[node];
    const int e = rowptr[node + 1];
    for (; b + 1 < e; b += 2) {
        int s0 = esrc[b],     s1 = esrc[b + 1];
        float n0 = enorm[b],  n1 = enorm[b + 1];
        float4 v0 = *(const float4*)(h + (size_t)s0 * C + tid * 4);
        float4 v1 = *(const float4*)(h + (size_t)s1 * C + tid * 4);
        acc.x += v0.x * n0; acc.y += v0.y * n0; acc.z += v0.z * n0; acc.w += v0.w * n0;
        acc.x += v1.x * n1; acc.y += v1.y * n1; acc.z += v1.z * n1; acc.w += v1.w * n1;
    }
    if (b < e) {
        int s0 = esrc[b];
        float n0 = enorm[b];
        float4 v0 = *(const float4*)(h + (size_t)s0 * C + tid * 4);
        acc.x += v0.x * n0; acc.y += v0.y * n0; acc.z += v0.z * n0; acc.w += v0.w * n0;
    }
    *(float4*)(out + (size_t)node * C + tid * 4) = acc;
}

// ---------------- BN / pool / misc ----------------

__global__ void bn_stats_kernel(const float* __restrict__ h,
                                float* __restrict__ sum, float* __restrict__ sumsq,
                                int n, int C) {
    int c = blockIdx.x * 256 + threadIdx.x;
    if (c >= C) return;
    int rowsPer = CEILDIV(n, gridDim.y);
    int r0 = blockIdx.y * rowsPer;
    int r1 = min(n, r0 + rowsPer);
    float s = 0.f, sq = 0.f;
    for (int r = r0; r < r1; r++) {
        float v = h[(size_t)r * C + c];
        s += v;
        sq += v * v;
    }
    atomicAdd(&sum[c], s);
    atomicAdd(&sumsq[c], sq);
}

__global__ void bn_apply_kernel(float* __restrict__ h,
                                const float* __restrict__ sum, const float* __restrict__ sumsq,
                                const float* __restrict__ gma, const float* __restrict__ bta,
                                int n, int C) {
    int idx = blockIdx.x * blockDim.x + threadIdx.x;
    if (idx >= n * C) return;
    int c = idx % C;
    float invn = 1.f / (float)n;
    float mean = sum[c] * invn;
    float var = sumsq[c] * invn - mean * mean;
    float y = (h[idx] - mean) * rsqrtf(var + 1e-5f) * gma[c] + bta[c];
    h[idx] = tanhf(y);
}

__global__ void node_dots_kernel(const float* __restrict__ h,
                                 const float* __restrict__ relw,
                                 const float* __restrict__ rootw,
                                 const float* __restrict__ relb,
                                 float* __restrict__ t, float* __restrict__ score,
                                 int n, int C) {
    int node = (blockIdx.x * blockDim.x + threadIdx.x) >> 5;
    int lane = threadIdx.x & 31;
    if (node >= n) return;
    const float* hp = h + (size_t)node * C;
    float a = 0.f, b = 0.f;
    for (int c = lane; c < C; c += 32) {
        float v = hp[c];
        a += v * relw[c];
        b += v * rootw[c];
    }
#pragma unroll
    for (int o = 16; o > 0; o >>= 1) {
        a += __shfl_down_sync(0xffffffffu, a, o);
        b += __shfl_down_sync(0xffffffffu, b, o);
    }
    if (lane == 0) {
        t[node] = a;
        score[node] = b + relb[0];
    }
}

__global__ void score_edge_kernel(const int* __restrict__ src, const int* __restrict__ dst,
                                  const float* __restrict__ ew, const float* __restrict__ t,
                                  float* __restrict__ score) {
    int e = blockIdx.x * blockDim.x + threadIdx.x;
    if (e >= ETOT) return;
    float w = ew[e];
    if (w != 0.f) atomicAdd(&score[dst[e]], w * t[src[e]]);
}

__global__ void init_newid_kernel(int* __restrict__ newid, int n) {
    int i = blockIdx.x * blockDim.x + threadIdx.x;
    if (i < n) newid[i] = -1;
}

template <int SZ>
__global__ void __launch_bounds__(512)
topk_kernel(const float* __restrict__ score, int n_per, int ksel,
            int* __restrict__ perm, float* __restrict__ gain, int* __restrict__ newid) {
    __shared__ float sk[SZ];
    __shared__ int si[SZ];
    const int g = blockIdx.x;
    const int tid = threadIdx.x;
    for (int i = tid; i < SZ; i += 512) {
        if (i < n_per) { sk[i] = score[g * n_per + i]; si[i] = i; }
        else           { sk[i] = -INFINITY;            si[i] = 0x40000000 + i; }
    }
    __syncthreads();
    for (int kk = 2; kk <= SZ; kk <<= 1) {
        for (int j = kk >> 1; j > 0; j >>= 1) {
            for (int i = tid; i < SZ; i += 512) {
                int ixj = i ^ j;
                if (ixj > i) {
                    bool up = ((i & kk) == 0);
                    float s1 = sk[i], s2 = sk[ixj];
                    int i1 = si[i], i2 = si[ixj];
                    bool after = (s1 < s2) || (s1 == s2 && i1 > i2);
                    if (up == after) {
                        sk[i] = s2; sk[ixj] = s1;
                        si[i] = i2; si[ixj] = i1;
                    }
                }
            }
            __syncthreads();
        }
    }
    for (int r = tid; r < ksel; r += 512) {
        int old = g * n_per + si[r];
        int ng = g * ksel + r;
        perm[ng] = old;
        gain[ng] = tanhf(sk[r]);
        newid[old] = ng;
    }
}

__global__ void gather_kernel(const float* __restrict__ hin, float* __restrict__ hout,
                              const int* __restrict__ perm, const float* __restrict__ gain,
                              int rows, int C4) {
    int idx = blockIdx.x * blockDim.x + threadIdx.x;
    if (idx >= rows * C4) return;
    int row = idx / C4;
    int c = idx - row * C4;
    float gn = gain[row];
    float4 v = ((const float4*)hin)[(size_t)perm[row] * C4 + c];
    v.x *= gn; v.y *= gn; v.z *= gn; v.w *= gn;
    ((float4*)hout)[idx] = v;
}

__global__ void remap_kernel(int* __restrict__ src, int* __restrict__ dst,
                             float* __restrict__ ew, const int* __restrict__ newid) {
    int e = blockIdx.x * blockDim.x + threadIdx.x;
    if (e >= ETOT) return;
    int ns = newid[src[e]];
    int nd = newid[dst[e]];
    bool keep = (ns >= 0) && (nd >= 0);
    src[e] = keep ? ns : 0;
    dst[e] = keep ? nd : 0;
    ew[e] = keep ? ew[e] : 0.f;
}

__global__ void readout_kernel(const float* __restrict__ h, float* __restrict__ out) {
    int g = blockIdx.x;
    int c = threadIdx.x;
    const float* p = h + (size_t)(g * K3) * 256 + c;
    float mx = -INFINITY, sm = 0.f;
    for (int i = 0; i < K3; i++) {
        float v = p[(size_t)i * 256];
        mx = fmaxf(mx, v);
        sm += v;
    }
    out[g * 512 + c] = mx;
    out[g * 512 + 256 + c] = sm / (float)K3;
}

// ---------------- host orchestration ----------------

extern "C" void kernel_launch(void* const* d_in, const int* in_sizes, int n_in,
                              void* d_out, int out_size) {
    const float* x    = (const float*)d_in[0];
    const int*   ei   = (const int*)d_in[1];
    const float* W1   = (const float*)d_in[2];
    const float* b1   = (const float*)d_in[3];
    const float* W2   = (const float*)d_in[4];
    const float* b2   = (const float*)d_in[5];
    const float* W3   = (const float*)d_in[6];
    const float* b3   = (const float*)d_in[7];
    const float* W4   = (const float*)d_in[8];
    const float* b4   = (const float*)d_in[9];
    const float* g1   = (const float*)d_in[10];
    const float* be1  = (const float*)d_in[11];
    const float* g2   = (const float*)d_in[12];
    const float* be2  = (const float*)d_in[13];
    const float* g3   = (const float*)d_in[14];
    const float* be3  = (const float*)d_in[15];
    const float* p1rw = (const float*)d_in[16];
    const float* p1rb = (const float*)d_in[17];
    const float* p1ow = (const float*)d_in[18];
    const float* p2rw = (const float*)d_in[19];
    const float* p2rb = (const float*)d_in[20];
    const float* p2ow = (const float*)d_in[21];
    const float* p3rw = (const float*)d_in[22];
    const float* p3rb = (const float*)d_in[23];
    const float* p3ow = (const float*)d_in[24];
    float* out = (float*)d_out;

    float *buf0, *buf1, *dis, *score, *t, *gain, *ew, *sum, *sumsq, *enorm;
    int *src, *dst, *newid, *perm, *icount, *rowptr, *cursor, *esrc, *blocksum, *blockoff;
    cudaGetSymbolAddress((void**)&buf0, g_buf0);
    cudaGetSymbolAddress((void**)&buf1, g_buf1);
    cudaGetSymbolAddress((void**)&dis, g_dis);
    cudaGetSymbolAddress((void**)&score, g_score);
    cudaGetSymbolAddress((void**)&t, g_t);
    cudaGetSymbolAddress((void**)&gain, g_gain);
    cudaGetSymbolAddress((void**)&ew, g_ew);
    cudaGetSymbolAddress((void**)&sum, g_sum);
    cudaGetSymbolAddress((void**)&sumsq, g_sumsq);
    cudaGetSymbolAddress((void**)&src, g_src);
    cudaGetSymbolAddress((void**)&dst, g_dst);
    cudaGetSymbolAddress((void**)&newid, g_newid);
    cudaGetSymbolAddress((void**)&perm, g_perm);
    cudaGetSymbolAddress((void**)&icount, g_icount);
    cudaGetSymbolAddress((void**)&rowptr, g_rowptr);
    cudaGetSymbolAddress((void**)&cursor, g_cursor);
    cudaGetSymbolAddress((void**)&esrc, g_esrc);
    cudaGetSymbolAddress((void**)&enorm, g_enorm);
    cudaGetSymbolAddress((void**)&blocksum, g_blocksum);
    cudaGetSymbolAddress((void**)&blockoff, g_blockoff);

    const int EB = CEILDIV(ETOT, 256);

    edge_init_kernel<<<EB, 256>>>(ei, src, dst, ew);

    auto gcn = [&](const float* in, float* hbuf, float* aggbuf,
                   int n, int Cin, int Cout,
                   const float* W, const float* b) {
        gemm_kernel<<<dim3(Cout / BN, CEILDIV(n, BM)), 256>>>(in, W, hbuf, n, Cin, Cout);
        cudaMemsetAsync(icount, 0, (size_t)n * sizeof(int));
        count_kernel<<<EB, 256>>>(dst, ew, icount);
        int nb = CEILDIV(n, 1024);
        scan_partial_kernel<<<nb, 1024>>>(icount, rowptr, blocksum, n);
        scan_blocksums_kernel<<<1, 32>>>(blocksum, blockoff, rowptr, nb, n);
        scan_finalize_kernel<<<nb, 1024>>>(icount, rowptr, blockoff, cursor, dis, n);
        fill_kernel<<<EB, 256>>>(src, dst, ew, dis, cursor, esrc, enorm);
        if (Cout == 512)
            gather_agg_kernel<512><<<n, 128>>>(hbuf, rowptr, esrc, enorm, b, aggbuf);
        else
            gather_agg_kernel<256><<<n, 64>>>(hbuf, rowptr, esrc, enorm, b, aggbuf);
    };
    auto bn_tanh = [&](float* hbuf, int n, int C, const float* gma, const float* bta) {
        cudaMemsetAsync(sum, 0, C * sizeof(float));
        cudaMemsetAsync(sumsq, 0, C * sizeof(float));
        bn_stats_kernel<<<dim3(CEILDIV(C, 256), 64), 256>>>(hbuf, sum, sumsq, n, C);
        bn_apply_kernel<<<CEILDIV(n * C, 256), 256>>>(hbuf, sum, sumsq, gma, bta, n, C);
    };
    auto pool_pre = [&](const float* hbuf, int n, int C,
                        const float* rw, const float* rb, const float* ow) {
        node_dots_kernel<<<CEILDIV(n * 32, 256), 256>>>(hbuf, rw, ow, rb, t, score, n, C);
        score_edge_kernel<<<EB, 256>>>(src, dst, ew, t, score);
        init_newid_kernel<<<CEILDIV(n, 256), 256>>>(newid, n);
    };
    auto pool_post = [&](const float* hbuf, float* outbuf, int ksel, int C) {
        int rows = BATCH * ksel;
        gather_kernel<<<CEILDIV(rows * (C / 4), 256), 256>>>(hbuf, outbuf, perm, gain,
                                                             rows, C / 4);
        remap_kernel<<<EB, 256>>>(src, dst, ew, newid);
    };

    // ---------- Layer 1 ----------
    gcn(x, buf1, buf0, N1, 512, 512, W1, b1);
    bn_tanh(buf0, N1, 512, g1, be1);
    pool_pre(buf0, N1, 512, p1rw, p1rb, p1ow);
    topk_kernel<1024><<<BATCH, 512>>>(score, 1024, K1, perm, gain, newid);
    pool_post(buf0, buf1, K1, 512);

    // ---------- Layer 2 ----------
    gcn(buf1, buf0, buf1, N2, 512, 512, W2, b2);
    bn_tanh(buf1, N2, 512, g2, be2);
    pool_pre(buf1, N2, 512, p2rw, p2rb, p2ow);
    topk_kernel<1024><<<BATCH, 512>>>(score, K1, K2, perm, gain, newid);
    pool_post(buf1, buf0, K2, 512);

    // ---------- Layer 3 ----------
    gcn(buf0, buf1, buf0, N3, 512, 256, W3, b3);
    bn_tanh(buf0, N3, 256, g3, be3);
    pool_pre(buf0, N3, 256, p3rw, p3rb, p3ow);
    topk_kernel<512><<<BATCH, 512>>>(score, K2, K3, perm, gain, newid);
    pool_post(buf0, buf1, K3, 256);

    // ---------- Layer 4 (no BN / pool) ----------
    gcn(buf1, buf0, buf1, N4, 256, 256, W4, b4);

    // ---------- readout ----------
    readout_kernel<<<BATCH, 256>>>(buf1, out);
    (void)in_sizes; (void)n_in; (void)out_size;
}

// round 8
// speedup vs baseline: 1.9576x; 1.4229x over previous
#include <cuda_runtime.h>
#include <cuda_bf16.h>
#include <mma.h>
#include <math.h>
#include <stdint.h>

using namespace nvcuda;

// ---------------- problem constants ----------------
#define BATCH   32
#define ETOT    262144
#define NMAX    32768
#define K1      615
#define K2      369
#define K3      185
#define N1      32768
#define N2      (BATCH*K1)      // 19680
#define N3      (BATCH*K2)      // 11808
#define N4      (BATCH*K3)      // 5920

#define CEILDIV(a,b) (((a)+(b)-1)/(b))

// ---------------- static device scratch ----------------
__device__ float g_buf0[(size_t)NMAX * 512];
__device__ float g_buf1[(size_t)NMAX * 512];
__device__ float g_dis[NMAX];
__device__ float g_score[NMAX];
__device__ float g_t[NMAX];
__device__ float g_gain[NMAX];
__device__ int   g_newid[NMAX];
__device__ int   g_perm[NMAX];
__device__ int   g_src[ETOT];
__device__ int   g_dst[ETOT];
__device__ float g_ew[ETOT];
__device__ float g_sum[512];
__device__ float g_sumsq[512];
// CSR scratch
__device__ int   g_icount[NMAX];
__device__ int   g_rowptr[NMAX + 1];
__device__ int   g_cursor[NMAX];
__device__ int   g_esrc[ETOT];
__device__ float g_enorm[ETOT];
__device__ int   g_blocksum[32];
__device__ int   g_blockoff[32];
// bf16 split-precision GEMM scratch
__device__ __nv_bfloat16 g_aHi[(size_t)NMAX * 512];
__device__ __nv_bfloat16 g_aLo[(size_t)NMAX * 512];
__device__ __nv_bfloat16 g_wHiT[512 * 512];
__device__ __nv_bfloat16 g_wLoT[512 * 512];

// ---------------- kernels ----------------

__global__ void edge_init_kernel(const int* __restrict__ ei,
                                 int* __restrict__ src, int* __restrict__ dst,
                                 float* __restrict__ ew) {
    int e = blockIdx.x * blockDim.x + threadIdx.x;
    if (e >= ETOT) return;
    src[e] = ei[e];
    dst[e] = ei[ETOT + e];
    ew[e]  = 1.0f;
}

// ---------------- bf16 split conversion ----------------

__global__ void convertA_kernel(const float4* __restrict__ A,
                                __nv_bfloat162* __restrict__ hi2,
                                __nv_bfloat162* __restrict__ lo2, int n4) {
    int i = blockIdx.x * blockDim.x + threadIdx.x;
    if (i >= n4) return;
    float4 v = A[i];
    __nv_bfloat16 h0 = __float2bfloat16(v.x);
    __nv_bfloat16 h1 = __float2bfloat16(v.y);
    __nv_bfloat16 h2 = __float2bfloat16(v.z);
    __nv_bfloat16 h3 = __float2bfloat16(v.w);
    __nv_bfloat16 l0 = __float2bfloat16(v.x - __bfloat162float(h0));
    __nv_bfloat16 l1 = __float2bfloat16(v.y - __bfloat162float(h1));
    __nv_bfloat16 l2 = __float2bfloat16(v.z - __bfloat162float(h2));
    __nv_bfloat16 l3 = __float2bfloat16(v.w - __bfloat162float(h3));
    hi2[2 * i]     = __halves2bfloat162(h0, h1);
    hi2[2 * i + 1] = __halves2bfloat162(h2, h3);
    lo2[2 * i]     = __halves2bfloat162(l0, l1);
    lo2[2 * i + 1] = __halves2bfloat162(l2, l3);
}

// W [K,N] fp32 -> WT_hi/lo [N,K] bf16 (output-coalesced)
__global__ void convertW_kernel(const float* __restrict__ W,
                                __nv_bfloat16* __restrict__ hiT,
                                __nv_bfloat16* __restrict__ loT, int K, int N) {
    int idx = blockIdx.x * blockDim.x + threadIdx.x;
    if (idx >= K * N) return;
    int n = idx / K, k = idx - n * K;
    float v = W[k * N + n];
    __nv_bfloat16 h = __float2bfloat16(v);
    __nv_bfloat16 l = __float2bfloat16(v - __bfloat162float(h));
    hiT[idx] = h;
    loT[idx] = l;
}

// ---------------------------------------------------------------
// WMMA bf16 split-precision GEMM: C[M,N] = A[M,K] @ B[K,N]
// A as Ahi/Alo bf16 [M,K]; B transposed as Bhi/Blo bf16 [N,K].
// 128x128 CTA tile, BK=32, 8 warps in 2(M)x4(N), warp tile 64x32.
// Accumulates Ahi*Bhi + Ahi*Blo + Alo*Bhi in fp32.
// N, K multiples of 32/128 as used here; M unguarded on stores
// (buffers are padded to a multiple of 128 rows).
// ---------------------------------------------------------------
#define TBM 128
#define TBN 128
#define TBK 32
#define WLDA 40   // padded smem leading dim (bf16 elems): 80B rows, 16B aligned

__global__ void __launch_bounds__(256)
wmma_gemm_kernel(const __nv_bfloat16* __restrict__ Ahi,
                 const __nv_bfloat16* __restrict__ Alo,
                 const __nv_bfloat16* __restrict__ Bhi,
                 const __nv_bfloat16* __restrict__ Blo,
                 float* __restrict__ C, int M, int K, int N) {
    __shared__ __nv_bfloat16 sAhi[TBM * WLDA];
    __shared__ __nv_bfloat16 sAlo[TBM * WLDA];
    __shared__ __nv_bfloat16 sBhi[TBN * WLDA];
    __shared__ __nv_bfloat16 sBlo[TBN * WLDA];

    const int tid = threadIdx.x;
    const int wid = tid >> 5;
    const int warpM = wid & 1;    // 0..1
    const int warpN = wid >> 1;   // 0..3
    const int mBase = blockIdx.y * TBM;
    const int nBase = blockIdx.x * TBN;

    wmma::fragment<wmma::accumulator, 16, 16, 16, float> acc[4][2];
#pragma unroll
    for (int i = 0; i < 4; i++)
#pragma unroll
        for (int j = 0; j < 2; j++) wmma::fill_fragment(acc[i][j], 0.f);

    const uint4 z = make_uint4(0u, 0u, 0u, 0u);

    for (int kc = 0; kc < K; kc += TBK) {
        // each tile: 128 rows x 32 bf16 = 512 x 16B; 2 quads per thread per tile
#pragma unroll
        for (int r = 0; r < 2; r++) {
            int f = tid + r * 256;
            int row = f >> 2;       // 0..127
            int q = f & 3;          // 16B quad in row
            int soff = row * WLDA + q * 8;
            int grow = mBase + row;
            uint4 vh = z, vl = z;
            if (grow < M) {
                const uint4* pa = (const uint4*)(Ahi + (size_t)grow * K + kc);
                const uint4* pl = (const uint4*)(Alo + (size_t)grow * K + kc);
                vh = pa[q];
                vl = pl[q];
            }
            *(uint4*)(sAhi + soff) = vh;
            *(uint4*)(sAlo + soff) = vl;
            int nrow = nBase + row;
            *(uint4*)(sBhi + soff) = ((const uint4*)(Bhi + (size_t)nrow * K + kc))[q];
            *(uint4*)(sBlo + soff) = ((const uint4*)(Blo + (size_t)nrow * K + kc))[q];
        }
        __syncthreads();

#pragma unroll
        for (int ks = 0; ks < TBK; ks += 16) {
            wmma::fragment<wmma::matrix_b, 16, 16, 16, __nv_bfloat16, wmma::col_major> bh[2], bl[2];
#pragma unroll
            for (int j = 0; j < 2; j++) {
                const __nv_bfloat16* bp = sBhi + (warpN * 32 + j * 16) * WLDA + ks;
                const __nv_bfloat16* lp = sBlo + (warpN * 32 + j * 16) * WLDA + ks;
                wmma::load_matrix_sync(bh[j], bp, WLDA);
                wmma::load_matrix_sync(bl[j], lp, WLDA);
            }
#pragma unroll
            for (int i = 0; i < 4; i++) {
                wmma::fragment<wmma::matrix_a, 16, 16, 16, __nv_bfloat16, wmma::row_major> ah, al;
                wmma::load_matrix_sync(ah, sAhi + (warpM * 64 + i * 16) * WLDA + ks, WLDA);
                wmma::load_matrix_sync(al, sAlo + (warpM * 64 + i * 16) * WLDA + ks, WLDA);
#pragma unroll
                for (int j = 0; j < 2; j++) wmma::mma_sync(acc[i][j], ah, bh[j], acc[i][j]);
#pragma unroll
                for (int j = 0; j < 2; j++) wmma::mma_sync(acc[i][j], ah, bl[j], acc[i][j]);
#pragma unroll
                for (int j = 0; j < 2; j++) wmma::mma_sync(acc[i][j], al, bh[j], acc[i][j]);
            }
        }
        __syncthreads();
    }

#pragma unroll
    for (int i = 0; i < 4; i++) {
        int r0 = mBase + warpM * 64 + i * 16;
#pragma unroll
        for (int j = 0; j < 2; j++) {
            float* cp = C + (size_t)r0 * N + nBase + warpN * 32 + j * 16;
            wmma::store_matrix_sync(cp, acc[i][j], N, wmma::mem_row_major);
        }
    }
}

// ---------------- CSR build ----------------

__global__ void count_kernel(const int* __restrict__ dst, const float* __restrict__ ew,
                             int* __restrict__ cnt) {
    int e = blockIdx.x * blockDim.x + threadIdx.x;
    if (e >= ETOT) return;
    if (ew[e] != 0.f) atomicAdd(&cnt[dst[e]], 1);
}

__global__ void __launch_bounds__(1024)
scan_partial_kernel(const int* __restrict__ cnt, int* __restrict__ rowptr,
                    int* __restrict__ blocksum, int n) {
    __shared__ int warpsum[32];
    const int tid = threadIdx.x;
    const int i = blockIdx.x * 1024 + tid;
    int v = (i < n) ? cnt[i] : 0;
    const int s = v;

    const int lane = tid & 31, wid = tid >> 5;
#pragma unroll
    for (int off = 1; off < 32; off <<= 1) {
        int u = __shfl_up_sync(0xffffffffu, v, off);
        if (lane >= off) v += u;
    }
    if (lane == 31) warpsum[wid] = v;
    __syncthreads();
    if (wid == 0) {
        int w = warpsum[lane];
#pragma unroll
        for (int off = 1; off < 32; off <<= 1) {
            int u = __shfl_up_sync(0xffffffffu, w, off);
            if (lane >= off) w += u;
        }
        warpsum[lane] = w;
    }
    __syncthreads();
    int excl = v - s + (wid > 0 ? warpsum[wid - 1] : 0);
    if (i < n) rowptr[i] = excl;
    if (tid == 1023) blocksum[blockIdx.x] = excl + s;
}

__global__ void scan_blocksums_kernel(const int* __restrict__ blocksum,
                                      int* __restrict__ blockoff,
                                      int* __restrict__ rowptr,
                                      int nblocks, int n) {
    const int lane = threadIdx.x;
    int v = (lane < nblocks) ? blocksum[lane] : 0;
    const int s = v;
#pragma unroll
    for (int off = 1; off < 32; off <<= 1) {
        int u = __shfl_up_sync(0xffffffffu, v, off);
        if (lane >= off) v += u;
    }
    if (lane < nblocks) blockoff[lane] = v - s;
    if (lane == 31) rowptr[n] = v;
}

__global__ void __launch_bounds__(1024)
scan_finalize_kernel(const int* __restrict__ cnt, int* __restrict__ rowptr,
                     const int* __restrict__ blockoff,
                     int* __restrict__ cursor, float* __restrict__ dis, int n) {
    const int i = blockIdx.x * 1024 + threadIdx.x;
    if (i >= n) return;
    int r = rowptr[i] + blockoff[blockIdx.x];
    rowptr[i] = r;
    cursor[i] = r;
    int c = cnt[i];
    dis[i] = (c > 0) ? rsqrtf((float)c) : 0.f;
}

__global__ void fill_kernel(const int* __restrict__ src, const int* __restrict__ dst,
                            const float* __restrict__ ew, const float* __restrict__ dis,
                            int* __restrict__ cursor,
                            int* __restrict__ esrc, float* __restrict__ enorm) {
    int e = blockIdx.x * blockDim.x + threadIdx.x;
    if (e >= ETOT) return;
    float w = ew[e];
    if (w == 0.f) return;
    int s = src[e], d = dst[e];
    int pos = atomicAdd(&cursor[d], 1);
    esrc[pos] = s;
    enorm[pos] = dis[s] * dis[d] * w;
}

template <int C>
__global__ void gather_agg_kernel(const float* __restrict__ h,
                                  const int* __restrict__ rowptr,
                                  const int* __restrict__ esrc,
                                  const float* __restrict__ enorm,
                                  const float* __restrict__ bias,
                                  float* __restrict__ out) {
    const int node = blockIdx.x;
    const int tid = threadIdx.x;
    float4 acc = *(const float4*)(bias + tid * 4);
    int b = rowptr[node];
    const int e = rowptr[node + 1];
    for (; b + 1 < e; b += 2) {
        int s0 = esrc[b],     s1 = esrc[b + 1];
        float n0 = enorm[b],  n1 = enorm[b + 1];
        float4 v0 = *(const float4*)(h + (size_t)s0 * C + tid * 4);
        float4 v1 = *(const float4*)(h + (size_t)s1 * C + tid * 4);
        acc.x += v0.x * n0; acc.y += v0.y * n0; acc.z += v0.z * n0; acc.w += v0.w * n0;
        acc.x += v1.x * n1; acc.y += v1.y * n1; acc.z += v1.z * n1; acc.w += v1.w * n1;
    }
    if (b < e) {
        int s0 = esrc[b];
        float n0 = enorm[b];
        float4 v0 = *(const float4*)(h + (size_t)s0 * C + tid * 4);
        acc.x += v0.x * n0; acc.y += v0.y * n0; acc.z += v0.z * n0; acc.w += v0.w * n0;
    }
    *(float4*)(out + (size_t)node * C + tid * 4) = acc;
}

// ---------------- BN / pool / misc ----------------

__global__ void bn_stats_kernel(const float* __restrict__ h,
                                float* __restrict__ sum, float* __restrict__ sumsq,
                                int n, int C) {
    int c = blockIdx.x * 256 + threadIdx.x;
    if (c >= C) return;
    int rowsPer = CEILDIV(n, gridDim.y);
    int r0 = blockIdx.y * rowsPer;
    int r1 = min(n, r0 + rowsPer);
    float s = 0.f, sq = 0.f;
    for (int r = r0; r < r1; r++) {
        float v = h[(size_t)r * C + c];
        s += v;
        sq += v * v;
    }
    atomicAdd(&sum[c], s);
    atomicAdd(&sumsq[c], sq);
}

__global__ void bn_apply_kernel(float* __restrict__ h,
                                const float* __restrict__ sum, const float* __restrict__ sumsq,
                                const float* __restrict__ gma, const float* __restrict__ bta,
                                int n, int C) {
    int idx = blockIdx.x * blockDim.x + threadIdx.x;
    if (idx >= n * C) return;
    int c = idx % C;
    float invn = 1.f / (float)n;
    float mean = sum[c] * invn;
    float var = sumsq[c] * invn - mean * mean;
    float y = (h[idx] - mean) * rsqrtf(var + 1e-5f) * gma[c] + bta[c];
    h[idx] = tanhf(y);
}

__global__ void node_dots_kernel(const float* __restrict__ h,
                                 const float* __restrict__ relw,
                                 const float* __restrict__ rootw,
                                 const float* __restrict__ relb,
                                 float* __restrict__ t, float* __restrict__ score,
                                 int n, int C) {
    int node = (blockIdx.x * blockDim.x + threadIdx.x) >> 5;
    int lane = threadIdx.x & 31;
    if (node >= n) return;
    const float* hp = h + (size_t)node * C;
    float a = 0.f, b = 0.f;
    for (int c = lane; c < C; c += 32) {
        float v = hp[c];
        a += v * relw[c];
        b += v * rootw[c];
    }
#pragma unroll
    for (int o = 16; o > 0; o >>= 1) {
        a += __shfl_down_sync(0xffffffffu, a, o);
        b += __shfl_down_sync(0xffffffffu, b, o);
    }
    if (lane == 0) {
        t[node] = a;
        score[node] = b + relb[0];
    }
}

__global__ void score_edge_kernel(const int* __restrict__ src, const int* __restrict__ dst,
                                  const float* __restrict__ ew, const float* __restrict__ t,
                                  float* __restrict__ score) {
    int e = blockIdx.x * blockDim.x + threadIdx.x;
    if (e >= ETOT) return;
    float w = ew[e];
    if (w != 0.f) atomicAdd(&score[dst[e]], w * t[src[e]]);
}

__global__ void init_newid_kernel(int* __restrict__ newid, int n) {
    int i = blockIdx.x * blockDim.x + threadIdx.x;
    if (i < n) newid[i] = -1;
}

template <int SZ>
__global__ void __launch_bounds__(512)
topk_kernel(const float* __restrict__ score, int n_per, int ksel,
            int* __restrict__ perm, float* __restrict__ gain, int* __restrict__ newid) {
    __shared__ float sk[SZ];
    __shared__ int si[SZ];
    const int g = blockIdx.x;
    const int tid = threadIdx.x;
    for (int i = tid; i < SZ; i += 512) {
        if (i < n_per) { sk[i] = score[g * n_per + i]; si[i] = i; }
        else           { sk[i] = -INFINITY;            si[i] = 0x40000000 + i; }
    }
    __syncthreads();
    for (int kk = 2; kk <= SZ; kk <<= 1) {
        for (int j = kk >> 1; j > 0; j >>= 1) {
            for (int i = tid; i < SZ; i += 512) {
                int ixj = i ^ j;
                if (ixj > i) {
                    bool up = ((i & kk) == 0);
                    float s1 = sk[i], s2 = sk[ixj];
                    int i1 = si[i], i2 = si[ixj];
                    bool after = (s1 < s2) || (s1 == s2 && i1 > i2);
                    if (up == after) {
                        sk[i] = s2; sk[ixj] = s1;
                        si[i] = i2; si[ixj] = i1;
                    }
                }
            }
            __syncthreads();
        }
    }
    for (int r = tid; r < ksel; r += 512) {
        int old = g * n_per + si[r];
        int ng = g * ksel + r;
        perm[ng] = old;
        gain[ng] = tanhf(sk[r]);
        newid[old] = ng;
    }
}

__global__ void gather_kernel(const float* __restrict__ hin, float* __restrict__ hout,
                              const int* __restrict__ perm, const float* __restrict__ gain,
                              int rows, int C4) {
    int idx = blockIdx.x * blockDim.x + threadIdx.x;
    if (idx >= rows * C4) return;
    int row = idx / C4;
    int c = idx - row * C4;
    float gn = gain[row];
    float4 v = ((const float4*)hin)[(size_t)perm[row] * C4 + c];
    v.x *= gn; v.y *= gn; v.z *= gn; v.w *= gn;
    ((float4*)hout)[idx] = v;
}

__global__ void remap_kernel(int* __restrict__ src, int* __restrict__ dst,
                             float* __restrict__ ew, const int* __restrict__ newid) {
    int e = blockIdx.x * blockDim.x + threadIdx.x;
    if (e >= ETOT) return;
    int ns = newid[src[e]];
    int nd = newid[dst[e]];
    bool keep = (ns >= 0) && (nd >= 0);
    src[e] = keep ? ns : 0;
    dst[e] = keep ? nd : 0;
    ew[e] = keep ? ew[e] : 0.f;
}

__global__ void readout_kernel(const float* __restrict__ h, float* __restrict__ out) {
    int g = blockIdx.x;
    int c = threadIdx.x;
    const float* p = h + (size_t)(g * K3) * 256 + c;
    float mx = -INFINITY, sm = 0.f;
    for (int i = 0; i < K3; i++) {
        float v = p[(size_t)i * 256];
        mx = fmaxf(mx, v);
        sm += v;
    }
    out[g * 512 + c] = mx;
    out[g * 512 + 256 + c] = sm / (float)K3;
}

// ---------------- host orchestration ----------------

extern "C" void kernel_launch(void* const* d_in, const int* in_sizes, int n_in,
                              void* d_out, int out_size) {
    const float* x    = (const float*)d_in[0];
    const int*   ei   = (const int*)d_in[1];
    const float* W1   = (const float*)d_in[2];
    const float* b1   = (const float*)d_in[3];
    const float* W2   = (const float*)d_in[4];
    const float* b2   = (const float*)d_in[5];
    const float* W3   = (const float*)d_in[6];
    const float* b3   = (const float*)d_in[7];
    const float* W4   = (const float*)d_in[8];
    const float* b4   = (const float*)d_in[9];
    const float* g1   = (const float*)d_in[10];
    const float* be1  = (const float*)d_in[11];
    const float* g2   = (const float*)d_in[12];
    const float* be2  = (const float*)d_in[13];
    const float* g3   = (const float*)d_in[14];
    const float* be3  = (const float*)d_in[15];
    const float* p1rw = (const float*)d_in[16];
    const float* p1rb = (const float*)d_in[17];
    const float* p1ow = (const float*)d_in[18];
    const float* p2rw = (const float*)d_in[19];
    const float* p2rb = (const float*)d_in[20];
    const float* p2ow = (const float*)d_in[21];
    const float* p3rw = (const float*)d_in[22];
    const float* p3rb = (const float*)d_in[23];
    const float* p3ow = (const float*)d_in[24];
    float* out = (float*)d_out;

    float *buf0, *buf1, *dis, *score, *t, *gain, *ew, *sum, *sumsq, *enorm;
    int *src, *dst, *newid, *perm, *icount, *rowptr, *cursor, *esrc, *blocksum, *blockoff;
    __nv_bfloat16 *aHi, *aLo, *wHiT, *wLoT;
    cudaGetSymbolAddress((void**)&buf0, g_buf0);
    cudaGetSymbolAddress((void**)&buf1, g_buf1);
    cudaGetSymbolAddress((void**)&dis, g_dis);
    cudaGetSymbolAddress((void**)&score, g_score);
    cudaGetSymbolAddress((void**)&t, g_t);
    cudaGetSymbolAddress((void**)&gain, g_gain);
    cudaGetSymbolAddress((void**)&ew, g_ew);
    cudaGetSymbolAddress((void**)&sum, g_sum);
    cudaGetSymbolAddress((void**)&sumsq, g_sumsq);
    cudaGetSymbolAddress((void**)&src, g_src);
    cudaGetSymbolAddress((void**)&dst, g_dst);
    cudaGetSymbolAddress((void**)&newid, g_newid);
    cudaGetSymbolAddress((void**)&perm, g_perm);
    cudaGetSymbolAddress((void**)&icount, g_icount);
    cudaGetSymbolAddress((void**)&rowptr, g_rowptr);
    cudaGetSymbolAddress((void**)&cursor, g_cursor);
    cudaGetSymbolAddress((void**)&esrc, g_esrc);
    cudaGetSymbolAddress((void**)&enorm, g_enorm);
    cudaGetSymbolAddress((void**)&blocksum, g_blocksum);
    cudaGetSymbolAddress((void**)&blockoff, g_blockoff);
    cudaGetSymbolAddress((void**)&aHi, g_aHi);
    cudaGetSymbolAddress((void**)&aLo, g_aLo);
    cudaGetSymbolAddress((void**)&wHiT, g_wHiT);
    cudaGetSymbolAddress((void**)&wLoT, g_wLoT);

    const int EB = CEILDIV(ETOT, 256);

    edge_init_kernel<<<EB, 256>>>(ei, src, dst, ew);

    auto gcn = [&](const float* in, float* hbuf, float* aggbuf,
                   int n, int Cin, int Cout,
                   const float* W, const float* b) {
        // bf16 split GEMM: hbuf = in @ W
        convertW_kernel<<<CEILDIV(Cin * Cout, 256), 256>>>(W, wHiT, wLoT, Cin, Cout);
        int n4 = n * Cin / 4;
        convertA_kernel<<<CEILDIV(n4, 256), 256>>>((const float4*)in,
                                                   (__nv_bfloat162*)aHi,
                                                   (__nv_bfloat162*)aLo, n4);
        wmma_gemm_kernel<<<dim3(Cout / TBN, CEILDIV(n, TBM)), 256>>>(
            aHi, aLo, wHiT, wLoT, hbuf, n, Cin, Cout);
        // CSR build + gather-aggregate
        cudaMemsetAsync(icount, 0, (size_t)n * sizeof(int));
        count_kernel<<<EB, 256>>>(dst, ew, icount);
        int nb = CEILDIV(n, 1024);
        scan_partial_kernel<<<nb, 1024>>>(icount, rowptr, blocksum, n);
        scan_blocksums_kernel<<<1, 32>>>(blocksum, blockoff, rowptr, nb, n);
        scan_finalize_kernel<<<nb, 1024>>>(icount, rowptr, blockoff, cursor, dis, n);
        fill_kernel<<<EB, 256>>>(src, dst, ew, dis, cursor, esrc, enorm);
        if (Cout == 512)
            gather_agg_kernel<512><<<n, 128>>>(hbuf, rowptr, esrc, enorm, b, aggbuf);
        else
            gather_agg_kernel<256><<<n, 64>>>(hbuf, rowptr, esrc, enorm, b, aggbuf);
    };
    auto bn_tanh = [&](float* hbuf, int n, int C, const float* gma, const float* bta) {
        cudaMemsetAsync(sum, 0, C * sizeof(float));
        cudaMemsetAsync(sumsq, 0, C * sizeof(float));
        bn_stats_kernel<<<dim3(CEILDIV(C, 256), 64), 256>>>(hbuf, sum, sumsq, n, C);
        bn_apply_kernel<<<CEILDIV(n * C, 256), 256>>>(hbuf, sum, sumsq, gma, bta, n, C);
    };
    auto pool_pre = [&](const float* hbuf, int n, int C,
                        const float* rw, const float* rb, const float* ow) {
        node_dots_kernel<<<CEILDIV(n * 32, 256), 256>>>(hbuf, rw, ow, rb, t, score, n, C);
        score_edge_kernel<<<EB, 256>>>(src, dst, ew, t, score);
        init_newid_kernel<<<CEILDIV(n, 256), 256>>>(newid, n);
    };
    auto pool_post = [&](const float* hbuf, float* outbuf, int ksel, int C) {
        int rows = BATCH * ksel;
        gather_kernel<<<CEILDIV(rows * (C / 4), 256), 256>>>(hbuf, outbuf, perm, gain,
                                                             rows, C / 4);
        remap_kernel<<<EB, 256>>>(src, dst, ew, newid);
    };

    // ---------- Layer 1 ----------
    gcn(x, buf1, buf0, N1, 512, 512, W1, b1);
    bn_tanh(buf0, N1, 512, g1, be1);
    pool_pre(buf0, N1, 512, p1rw, p1rb, p1ow);
    topk_kernel<1024><<<BATCH, 512>>>(score, 1024, K1, perm, gain, newid);
    pool_post(buf0, buf1, K1, 512);

    // ---------- Layer 2 ----------
    gcn(buf1, buf0, buf1, N2, 512, 512, W2, b2);
    bn_tanh(buf1, N2, 512, g2, be2);
    pool_pre(buf1, N2, 512, p2rw, p2rb, p2ow);
    topk_kernel<1024><<<BATCH, 512>>>(score, K1, K2, perm, gain, newid);
    pool_post(buf1, buf0, K2, 512);

    // ---------- Layer 3 ----------
    gcn(buf0, buf1, buf0, N3, 512, 256, W3, b3);
    bn_tanh(buf0, N3, 256, g3, be3);
    pool_pre(buf0, N3, 256, p3rw, p3rb, p3ow);
    topk_kernel<512><<<BATCH, 512>>>(score, K2, K3, perm, gain, newid);
    pool_post(buf0, buf1, K3, 256);

    // ---------- Layer 4 (no BN / pool) ----------
    gcn(buf1, buf0, buf1, N4, 256, 256, W4, b4);

    // ---------- readout ----------
    readout_kernel<<<BATCH, 256>>>(buf1, out);
    (void)in_sizes; (void)n_in; (void)out_size;
}

// round 9
// speedup vs baseline: 2.3697x; 1.2105x over previous
#include <cuda_runtime.h>
#include <cuda_bf16.h>
#include <mma.h>
#include <math.h>
#include <stdint.h>

using namespace nvcuda;

// ---------------- problem constants ----------------
#define BATCH   32
#define ETOT    262144
#define NMAX    32768
#define K1      615
#define K2      369
#define K3      185
#define N1      32768
#define N2      (BATCH*K1)      // 19680
#define N3      (BATCH*K2)      // 11808
#define N4      (BATCH*K3)      // 5920

#define CEILDIV(a,b) (((a)+(b)-1)/(b))

// ---------------- static device scratch ----------------
__device__ float g_buf0[(size_t)NMAX * 512];
__device__ float g_buf1[(size_t)NMAX * 512];
__device__ float g_dis[NMAX];
__device__ float g_score[NMAX];
__device__ float g_t[NMAX];
__device__ float g_gain[NMAX];
__device__ int   g_newid[NMAX];
__device__ int   g_perm[NMAX];
__device__ int   g_src[ETOT];
__device__ int   g_dst[ETOT];
__device__ float g_ew[ETOT];
__device__ float g_sum[512];
__device__ float g_sumsq[512];
// CSR scratch
__device__ int   g_icount[NMAX];
__device__ int   g_rowptr[NMAX + 1];
__device__ int   g_cursor[NMAX];
__device__ int   g_esrc[ETOT];
__device__ float g_enorm[ETOT];
__device__ int   g_blocksum[32];
__device__ int   g_blockoff[32];
// bf16 split-precision GEMM scratch
__device__ __nv_bfloat16 g_aHi[(size_t)NMAX * 512];
__device__ __nv_bfloat16 g_aLo[(size_t)NMAX * 512];
__device__ __nv_bfloat16 g_wHiT[512 * 512];
__device__ __nv_bfloat16 g_wLoT[512 * 512];

// ---------------- kernels ----------------

__global__ void edge_init_kernel(const int* __restrict__ ei,
                                 int* __restrict__ src, int* __restrict__ dst,
                                 float* __restrict__ ew) {
    int e = blockIdx.x * blockDim.x + threadIdx.x;
    if (e >= ETOT) return;
    src[e] = ei[e];
    dst[e] = ei[ETOT + e];
    ew[e]  = 1.0f;
}

// ---------------- bf16 split conversion ----------------

__global__ void convertA_kernel(const float4* __restrict__ A,
                                __nv_bfloat162* __restrict__ hi2,
                                __nv_bfloat162* __restrict__ lo2, int n4) {
    int i = blockIdx.x * blockDim.x + threadIdx.x;
    if (i >= n4) return;
    float4 v = A[i];
    __nv_bfloat16 h0 = __float2bfloat16(v.x);
    __nv_bfloat16 h1 = __float2bfloat16(v.y);
    __nv_bfloat16 h2 = __float2bfloat16(v.z);
    __nv_bfloat16 h3 = __float2bfloat16(v.w);
    __nv_bfloat16 l0 = __float2bfloat16(v.x - __bfloat162float(h0));
    __nv_bfloat16 l1 = __float2bfloat16(v.y - __bfloat162float(h1));
    __nv_bfloat16 l2 = __float2bfloat16(v.z - __bfloat162float(h2));
    __nv_bfloat16 l3 = __float2bfloat16(v.w - __bfloat162float(h3));
    hi2[2 * i]     = __halves2bfloat162(h0, h1);
    hi2[2 * i + 1] = __halves2bfloat162(h2, h3);
    lo2[2 * i]     = __halves2bfloat162(l0, l1);
    lo2[2 * i + 1] = __halves2bfloat162(l2, l3);
}

// W [K,N] fp32 -> WT_hi/lo [N,K] bf16 (output-coalesced)
__global__ void convertW_kernel(const float* __restrict__ W,
                                __nv_bfloat16* __restrict__ hiT,
                                __nv_bfloat16* __restrict__ loT, int K, int N) {
    int idx = blockIdx.x * blockDim.x + threadIdx.x;
    if (idx >= K * N) return;
    int n = idx / K, k = idx - n * K;
    float v = W[k * N + n];
    __nv_bfloat16 h = __float2bfloat16(v);
    __nv_bfloat16 l = __float2bfloat16(v - __bfloat162float(h));
    hiT[idx] = h;
    loT[idx] = l;
}

// ---------------------------------------------------------------
// WMMA bf16 split-precision GEMM v2: cp.async double-buffered.
// C[M,N] = A[M,K] @ B[K,N]; A as Ahi/Alo [M,K]; B transposed Bhi/Blo [N,K].
// CTA tile 128x128, stage depth TBK=16, 8 warps 2(M)x4(N), warp tile 64x32.
// Acc = Ahi*Bhi + Ahi*Blo + Alo*Bhi in fp32.
// ---------------------------------------------------------------
#define TBM 128
#define TBN 128
#define WLDA 24   // 48B rows: conflict-free ldmatrix, 16B aligned
// per stage: 4 tiles x 128 x WLDA bf16 = 4*3072 elems = 24576 B; 2 stages = 48 KB

__device__ __forceinline__ void cp16(uint32_t s, const void* g, int sz) {
    asm volatile("cp.async.cg.shared.global [%0], [%1], 16, %2;"
                 :: "r"(s), "l"(g), "r"(sz));
}

__global__ void __launch_bounds__(256, 2)
wmma_gemm_kernel(const __nv_bfloat16* __restrict__ Ahi,
                 const __nv_bfloat16* __restrict__ Alo,
                 const __nv_bfloat16* __restrict__ Bhi,
                 const __nv_bfloat16* __restrict__ Blo,
                 float* __restrict__ C, int M, int K, int N) {
    __shared__ __nv_bfloat16 sm[2 * 4 * 128 * WLDA];

    const int tid = threadIdx.x;
    const int wid = tid >> 5;
    const int warpM = wid & 1;
    const int warpN = wid >> 1;
    const int mBase = blockIdx.y * TBM;
    const int nBase = blockIdx.x * TBN;

    wmma::fragment<wmma::accumulator, 16, 16, 16, float> acc[4][2];
#pragma unroll
    for (int i = 0; i < 4; i++)
#pragma unroll
        for (int j = 0; j < 2; j++) wmma::fill_fragment(acc[i][j], 0.f);

    const uint32_t sbase = (uint32_t)__cvta_generic_to_shared(sm);
    const int row = tid >> 1, q = tid & 1;   // 128 rows x 2 16B-chunks per tile
    const int grow = mBase + row;
    const int nrow = nBase + row;
    const size_t aoff = (size_t)(grow < M ? grow : 0) * K + q * 8;
    const size_t boff = (size_t)nrow * K + q * 8;
    const int szA = (grow < M) ? 16 : 0;
    const uint32_t so = sbase + (uint32_t)(row * WLDA + q * 8) * 2;

    // stage load: stage s covers K range [kc, kc+16)
#define LOAD_STAGE(s, kc) do { \
        uint32_t s0 = so + (uint32_t)(s) * 24576u; \
        cp16(s0,          Ahi + aoff + (kc), szA); \
        cp16(s0 + 6144u,  Alo + aoff + (kc), szA); \
        cp16(s0 + 12288u, Bhi + boff + (kc), 16); \
        cp16(s0 + 18432u, Blo + boff + (kc), 16); \
    } while (0)

    LOAD_STAGE(0, 0);
    asm volatile("cp.async.commit_group;" ::: "memory");

    const int nCh = K >> 4;
    for (int ch = 0; ch < nCh; ch++) {
        if (ch + 1 < nCh) {
            LOAD_STAGE((ch + 1) & 1, (ch + 1) << 4);
            asm volatile("cp.async.commit_group;" ::: "memory");
            asm volatile("cp.async.wait_group 1;" ::: "memory");
        } else {
            asm volatile("cp.async.wait_group 0;" ::: "memory");
        }
        __syncthreads();

        const __nv_bfloat16* sAhi = sm + (ch & 1) * 12288;
        const __nv_bfloat16* sAlo = sAhi + 3072;
        const __nv_bfloat16* sBhi = sAlo + 3072;
        const __nv_bfloat16* sBlo = sBhi + 3072;

        wmma::fragment<wmma::matrix_b, 16, 16, 16, __nv_bfloat16, wmma::col_major> bh[2], bl[2];
#pragma unroll
        for (int j = 0; j < 2; j++) {
            wmma::load_matrix_sync(bh[j], sBhi + (warpN * 32 + j * 16) * WLDA, WLDA);
            wmma::load_matrix_sync(bl[j], sBlo + (warpN * 32 + j * 16) * WLDA, WLDA);
        }
#pragma unroll
        for (int i = 0; i < 4; i++) {
            wmma::fragment<wmma::matrix_a, 16, 16, 16, __nv_bfloat16, wmma::row_major> ah, al;
            wmma::load_matrix_sync(ah, sAhi + (warpM * 64 + i * 16) * WLDA, WLDA);
            wmma::load_matrix_sync(al, sAlo + (warpM * 64 + i * 16) * WLDA, WLDA);
#pragma unroll
            for (int j = 0; j < 2; j++) wmma::mma_sync(acc[i][j], ah, bh[j], acc[i][j]);
#pragma unroll
            for (int j = 0; j < 2; j++) wmma::mma_sync(acc[i][j], ah, bl[j], acc[i][j]);
#pragma unroll
            for (int j = 0; j < 2; j++) wmma::mma_sync(acc[i][j], al, bh[j], acc[i][j]);
        }
        __syncthreads();
    }
#undef LOAD_STAGE

#pragma unroll
    for (int i = 0; i < 4; i++) {
        int r0 = mBase + warpM * 64 + i * 16;
#pragma unroll
        for (int j = 0; j < 2; j++) {
            float* cp = C + (size_t)r0 * N + nBase + warpN * 32 + j * 16;
            wmma::store_matrix_sync(cp, acc[i][j], N, wmma::mem_row_major);
        }
    }
}

// ---------------- CSR build ----------------

__global__ void count_kernel(const int* __restrict__ dst, const float* __restrict__ ew,
                             int* __restrict__ cnt) {
    int e = blockIdx.x * blockDim.x + threadIdx.x;
    if (e >= ETOT) return;
    if (ew[e] != 0.f) atomicAdd(&cnt[dst[e]], 1);
}

__global__ void __launch_bounds__(1024)
scan_partial_kernel(const int* __restrict__ cnt, int* __restrict__ rowptr,
                    int* __restrict__ blocksum, int n) {
    __shared__ int warpsum[32];
    const int tid = threadIdx.x;
    const int i = blockIdx.x * 1024 + tid;
    int v = (i < n) ? cnt[i] : 0;
    const int s = v;

    const int lane = tid & 31, wid = tid >> 5;
#pragma unroll
    for (int off = 1; off < 32; off <<= 1) {
        int u = __shfl_up_sync(0xffffffffu, v, off);
        if (lane >= off) v += u;
    }
    if (lane == 31) warpsum[wid] = v;
    __syncthreads();
    if (wid == 0) {
        int w = warpsum[lane];
#pragma unroll
        for (int off = 1; off < 32; off <<= 1) {
            int u = __shfl_up_sync(0xffffffffu, w, off);
            if (lane >= off) w += u;
        }
        warpsum[lane] = w;
    }
    __syncthreads();
    int excl = v - s + (wid > 0 ? warpsum[wid - 1] : 0);
    if (i < n) rowptr[i] = excl;
    if (tid == 1023) blocksum[blockIdx.x] = excl + s;
}

__global__ void scan_blocksums_kernel(const int* __restrict__ blocksum,
                                      int* __restrict__ blockoff,
                                      int* __restrict__ rowptr,
                                      int nblocks, int n) {
    const int lane = threadIdx.x;
    int v = (lane < nblocks) ? blocksum[lane] : 0;
    const int s = v;
#pragma unroll
    for (int off = 1; off < 32; off <<= 1) {
        int u = __shfl_up_sync(0xffffffffu, v, off);
        if (lane >= off) v += u;
    }
    if (lane < nblocks) blockoff[lane] = v - s;
    if (lane == 31) rowptr[n] = v;
}

__global__ void __launch_bounds__(1024)
scan_finalize_kernel(const int* __restrict__ cnt, int* __restrict__ rowptr,
                     const int* __restrict__ blockoff,
                     int* __restrict__ cursor, float* __restrict__ dis, int n) {
    const int i = blockIdx.x * 1024 + threadIdx.x;
    if (i >= n) return;
    int r = rowptr[i] + blockoff[blockIdx.x];
    rowptr[i] = r;
    cursor[i] = r;
    int c = cnt[i];
    dis[i] = (c > 0) ? rsqrtf((float)c) : 0.f;
}

__global__ void fill_kernel(const int* __restrict__ src, const int* __restrict__ dst,
                            const float* __restrict__ ew, const float* __restrict__ dis,
                            int* __restrict__ cursor,
                            int* __restrict__ esrc, float* __restrict__ enorm) {
    int e = blockIdx.x * blockDim.x + threadIdx.x;
    if (e >= ETOT) return;
    float w = ew[e];
    if (w == 0.f) return;
    int s = src[e], d = dst[e];
    int pos = atomicAdd(&cursor[d], 1);
    esrc[pos] = s;
    enorm[pos] = dis[s] * dis[d] * w;
}

template <int C>
__global__ void gather_agg_kernel(const float* __restrict__ h,
                                  const int* __restrict__ rowptr,
                                  const int* __restrict__ esrc,
                                  const float* __restrict__ enorm,
                                  const float* __restrict__ bias,
                                  float* __restrict__ out) {
    const int node = blockIdx.x;
    const int tid = threadIdx.x;
    float4 acc = *(const float4*)(bias + tid * 4);
    int b = rowptr[node];
    const int e = rowptr[node + 1];
    for (; b + 1 < e; b += 2) {
        int s0 = esrc[b],     s1 = esrc[b + 1];
        float n0 = enorm[b],  n1 = enorm[b + 1];
        float4 v0 = *(const float4*)(h + (size_t)s0 * C + tid * 4);
        float4 v1 = *(const float4*)(h + (size_t)s1 * C + tid * 4);
        acc.x += v0.x * n0; acc.y += v0.y * n0; acc.z += v0.z * n0; acc.w += v0.w * n0;
        acc.x += v1.x * n1; acc.y += v1.y * n1; acc.z += v1.z * n1; acc.w += v1.w * n1;
    }
    if (b < e) {
        int s0 = esrc[b];
        float n0 = enorm[b];
        float4 v0 = *(const float4*)(h + (size_t)s0 * C + tid * 4);
        acc.x += v0.x * n0; acc.y += v0.y * n0; acc.z += v0.z * n0; acc.w += v0.w * n0;
    }
    *(float4*)(out + (size_t)node * C + tid * 4) = acc;
}

// ---------------- BN / pool / misc ----------------

__global__ void bn_stats_kernel(const float* __restrict__ h,
                                float* __restrict__ sum, float* __restrict__ sumsq,
                                int n, int C) {
    int c = blockIdx.x * 256 + threadIdx.x;
    if (c >= C) return;
    int rowsPer = CEILDIV(n, gridDim.y);
    int r0 = blockIdx.y * rowsPer;
    int r1 = min(n, r0 + rowsPer);
    float s = 0.f, sq = 0.f;
    for (int r = r0; r < r1; r++) {
        float v = h[(size_t)r * C + c];
        s += v;
        sq += v * v;
    }
    atomicAdd(&sum[c], s);
    atomicAdd(&sumsq[c], sq);
}

// fused BN(apply)+tanh + pool dot-products; warp per node
__global__ void bn_dots_kernel(float* __restrict__ h,
                               const float* __restrict__ sum, const float* __restrict__ sumsq,
                               const float* __restrict__ gma, const float* __restrict__ bta,
                               const float* __restrict__ relw, const float* __restrict__ rootw,
                               const float* __restrict__ relb,
                               float* __restrict__ t, float* __restrict__ score,
                               int n, int C) {
    int node = (blockIdx.x * blockDim.x + threadIdx.x) >> 5;
    int lane = threadIdx.x & 31;
    if (node >= n) return;
    float* hp = h + (size_t)node * C;
    const float invn = 1.f / (float)n;
    float a = 0.f, b = 0.f;
    for (int c = lane; c < C; c += 32) {
        float mean = sum[c] * invn;
        float var = sumsq[c] * invn - mean * mean;
        float y = tanhf((hp[c] - mean) * rsqrtf(var + 1e-5f) * gma[c] + bta[c]);
        hp[c] = y;
        a += y * relw[c];
        b += y * rootw[c];
    }
#pragma unroll
    for (int o = 16; o > 0; o >>= 1) {
        a += __shfl_down_sync(0xffffffffu, a, o);
        b += __shfl_down_sync(0xffffffffu, b, o);
    }
    if (lane == 0) {
        t[node] = a;
        score[node] = b + relb[0];
    }
}

__global__ void score_edge_kernel(const int* __restrict__ src, const int* __restrict__ dst,
                                  const float* __restrict__ ew, const float* __restrict__ t,
                                  float* __restrict__ score) {
    int e = blockIdx.x * blockDim.x + threadIdx.x;
    if (e >= ETOT) return;
    float w = ew[e];
    if (w != 0.f) atomicAdd(&score[dst[e]], w * t[src[e]]);
}

__global__ void init_newid_kernel(int* __restrict__ newid, int n) {
    int i = blockIdx.x * blockDim.x + threadIdx.x;
    if (i < n) newid[i] = -1;
}

template <int SZ>
__global__ void __launch_bounds__(512)
topk_kernel(const float* __restrict__ score, int n_per, int ksel,
            int* __restrict__ perm, float* __restrict__ gain, int* __restrict__ newid) {
    __shared__ float sk[SZ];
    __shared__ int si[SZ];
    const int g = blockIdx.x;
    const int tid = threadIdx.x;
    for (int i = tid; i < SZ; i += 512) {
        if (i < n_per) { sk[i] = score[g * n_per + i]; si[i] = i; }
        else           { sk[i] = -INFINITY;            si[i] = 0x40000000 + i; }
    }
    __syncthreads();
    for (int kk = 2; kk <= SZ; kk <<= 1) {
        for (int j = kk >> 1; j > 0; j >>= 1) {
            for (int i = tid; i < SZ; i += 512) {
                int ixj = i ^ j;
                if (ixj > i) {
                    bool up = ((i & kk) == 0);
                    float s1 = sk[i], s2 = sk[ixj];
                    int i1 = si[i], i2 = si[ixj];
                    bool after = (s1 < s2) || (s1 == s2 && i1 > i2);
                    if (up == after) {
                        sk[i] = s2; sk[ixj] = s1;
                        si[i] = i2; si[ixj] = i1;
                    }
                }
            }
            __syncthreads();
        }
    }
    for (int r = tid; r < ksel; r += 512) {
        int old = g * n_per + si[r];
        int ng = g * ksel + r;
        perm[ng] = old;
        gain[ng] = tanhf(sk[r]);
        newid[old] = ng;
    }
}

// pool gather fused with bf16 hi/lo split: x_new = h[perm]*tanh(score[perm])
__global__ void gather_split_kernel(const float* __restrict__ hin,
                                    __nv_bfloat16* __restrict__ hi,
                                    __nv_bfloat16* __restrict__ lo,
                                    const int* __restrict__ perm,
                                    const float* __restrict__ gain,
                                    int rows, int C4) {
    int idx = blockIdx.x * blockDim.x + threadIdx.x;
    if (idx >= rows * C4) return;
    int row = idx / C4;
    int c = idx - row * C4;
    float gn = gain[row];
    float4 v = ((const float4*)hin)[(size_t)perm[row] * C4 + c];
    v.x *= gn; v.y *= gn; v.z *= gn; v.w *= gn;
    __nv_bfloat16 h0 = __float2bfloat16(v.x);
    __nv_bfloat16 h1 = __float2bfloat16(v.y);
    __nv_bfloat16 h2 = __float2bfloat16(v.z);
    __nv_bfloat16 h3 = __float2bfloat16(v.w);
    __nv_bfloat162* hp = (__nv_bfloat162*)(hi) + 2 * idx;
    __nv_bfloat162* lp = (__nv_bfloat162*)(lo) + 2 * idx;
    hp[0] = __halves2bfloat162(h0, h1);
    hp[1] = __halves2bfloat162(h2, h3);
    lp[0] = __halves2bfloat162(__float2bfloat16(v.x - __bfloat162float(h0)),
                               __float2bfloat16(v.y - __bfloat162float(h1)));
    lp[1] = __halves2bfloat162(__float2bfloat16(v.z - __bfloat162float(h2)),
                               __float2bfloat16(v.w - __bfloat162float(h3)));
}

__global__ void remap_kernel(int* __restrict__ src, int* __restrict__ dst,
                             float* __restrict__ ew, const int* __restrict__ newid) {
    int e = blockIdx.x * blockDim.x + threadIdx.x;
    if (e >= ETOT) return;
    int ns = newid[src[e]];
    int nd = newid[dst[e]];
    bool keep = (ns >= 0) && (nd >= 0);
    src[e] = keep ? ns : 0;
    dst[e] = keep ? nd : 0;
    ew[e] = keep ? ew[e] : 0.f;
}

__global__ void readout_kernel(const float* __restrict__ h, float* __restrict__ out) {
    int g = blockIdx.x;
    int c = threadIdx.x;
    const float* p = h + (size_t)(g * K3) * 256 + c;
    float mx = -INFINITY, sm = 0.f;
    for (int i = 0; i < K3; i++) {
        float v = p[(size_t)i * 256];
        mx = fmaxf(mx, v);
        sm += v;
    }
    out[g * 512 + c] = mx;
    out[g * 512 + 256 + c] = sm / (float)K3;
}

// ---------------- host orchestration ----------------

extern "C" void kernel_launch(void* const* d_in, const int* in_sizes, int n_in,
                              void* d_out, int out_size) {
    const float* x    = (const float*)d_in[0];
    const int*   ei   = (const int*)d_in[1];
    const float* W1   = (const float*)d_in[2];
    const float* b1   = (const float*)d_in[3];
    const float* W2   = (const float*)d_in[4];
    const float* b2   = (const float*)d_in[5];
    const float* W3   = (const float*)d_in[6];
    const float* b3   = (const float*)d_in[7];
    const float* W4   = (const float*)d_in[8];
    const float* b4   = (const float*)d_in[9];
    const float* g1   = (const float*)d_in[10];
    const float* be1  = (const float*)d_in[11];
    const float* g2   = (const float*)d_in[12];
    const float* be2  = (const float*)d_in[13];
    const float* g3   = (const float*)d_in[14];
    const float* be3  = (const float*)d_in[15];
    const float* p1rw = (const float*)d_in[16];
    const float* p1rb = (const float*)d_in[17];
    const float* p1ow = (const float*)d_in[18];
    const float* p2rw = (const float*)d_in[19];
    const float* p2rb = (const float*)d_in[20];
    const float* p2ow = (const float*)d_in[21];
    const float* p3rw = (const float*)d_in[22];
    const float* p3rb = (const float*)d_in[23];
    const float* p3ow = (const float*)d_in[24];
    float* out = (float*)d_out;

    float *buf0, *buf1, *dis, *score, *t, *gain, *ew, *sum, *sumsq, *enorm;
    int *src, *dst, *newid, *perm, *icount, *rowptr, *cursor, *esrc, *blocksum, *blockoff;
    __nv_bfloat16 *aHi, *aLo, *wHiT, *wLoT;
    cudaGetSymbolAddress((void**)&buf0, g_buf0);
    cudaGetSymbolAddress((void**)&buf1, g_buf1);
    cudaGetSymbolAddress((void**)&dis, g_dis);
    cudaGetSymbolAddress((void**)&score, g_score);
    cudaGetSymbolAddress((void**)&t, g_t);
    cudaGetSymbolAddress((void**)&gain, g_gain);
    cudaGetSymbolAddress((void**)&ew, g_ew);
    cudaGetSymbolAddress((void**)&sum, g_sum);
    cudaGetSymbolAddress((void**)&sumsq, g_sumsq);
    cudaGetSymbolAddress((void**)&src, g_src);
    cudaGetSymbolAddress((void**)&dst, g_dst);
    cudaGetSymbolAddress((void**)&newid, g_newid);
    cudaGetSymbolAddress((void**)&perm, g_perm);
    cudaGetSymbolAddress((void**)&icount, g_icount);
    cudaGetSymbolAddress((void**)&rowptr, g_rowptr);
    cudaGetSymbolAddress((void**)&cursor, g_cursor);
    cudaGetSymbolAddress((void**)&esrc, g_esrc);
    cudaGetSymbolAddress((void**)&enorm, g_enorm);
    cudaGetSymbolAddress((void**)&blocksum, g_blocksum);
    cudaGetSymbolAddress((void**)&blockoff, g_blockoff);
    cudaGetSymbolAddress((void**)&aHi, g_aHi);
    cudaGetSymbolAddress((void**)&aLo, g_aLo);
    cudaGetSymbolAddress((void**)&wHiT, g_wHiT);
    cudaGetSymbolAddress((void**)&wLoT, g_wLoT);

    const int EB = CEILDIV(ETOT, 256);

    edge_init_kernel<<<EB, 256>>>(ei, src, dst, ew);

    // gcn: GEMM (aHi/aLo already populated) -> buf1; CSR; gather-agg -> buf0
    auto gcn = [&](int n, int Cin, int Cout, const float* W, const float* b) {
        convertW_kernel<<<CEILDIV(Cin * Cout, 256), 256>>>(W, wHiT, wLoT, Cin, Cout);
        wmma_gemm_kernel<<<dim3(Cout / TBN, CEILDIV(n, TBM)), 256>>>(
            aHi, aLo, wHiT, wLoT, buf1, n, Cin, Cout);
        cudaMemsetAsync(icount, 0, (size_t)n * sizeof(int));
        count_kernel<<<EB, 256>>>(dst, ew, icount);
        int nb = CEILDIV(n, 1024);
        scan_partial_kernel<<<nb, 1024>>>(icount, rowptr, blocksum, n);
        scan_blocksums_kernel<<<1, 32>>>(blocksum, blockoff, rowptr, nb, n);
        scan_finalize_kernel<<<nb, 1024>>>(icount, rowptr, blockoff, cursor, dis, n);
        fill_kernel<<<EB, 256>>>(src, dst, ew, dis, cursor, esrc, enorm);
        if (Cout == 512)
            gather_agg_kernel<512><<<n, 128>>>(buf1, rowptr, esrc, enorm, b, buf0);
        else
            gather_agg_kernel<256><<<n, 64>>>(buf1, rowptr, esrc, enorm, b, buf0);
    };
    // BN stats + fused BN-apply/tanh/dots on buf0
    auto bn_pool_pre = [&](int n, int C, const float* gma, const float* bta,
                           const float* rw, const float* rb, const float* ow) {
        cudaMemsetAsync(sum, 0, C * sizeof(float));
        cudaMemsetAsync(sumsq, 0, C * sizeof(float));
        bn_stats_kernel<<<dim3(CEILDIV(C, 256), 64), 256>>>(buf0, sum, sumsq, n, C);
        bn_dots_kernel<<<CEILDIV(n * 32, 256), 256>>>(buf0, sum, sumsq, gma, bta,
                                                      rw, ow, rb, t, score, n, C);
        score_edge_kernel<<<EB, 256>>>(src, dst, ew, t, score);
        init_newid_kernel<<<CEILDIV(n, 256), 256>>>(newid, n);
    };
    auto pool_post = [&](int ksel, int C) {
        int rows = BATCH * ksel;
        gather_split_kernel<<<CEILDIV(rows * (C / 4), 256), 256>>>(
            buf0, aHi, aLo, perm, gain, rows, C / 4);
        remap_kernel<<<EB, 256>>>(src, dst, ew, newid);
    };

    // ---------- Layer 1 ----------
    {
        int n4 = N1 * 512 / 4;
        convertA_kernel<<<CEILDIV(n4, 256), 256>>>((const float4*)x,
                                                   (__nv_bfloat162*)aHi,
                                                   (__nv_bfloat162*)aLo, n4);
    }
    gcn(N1, 512, 512, W1, b1);
    bn_pool_pre(N1, 512, g1, be1, p1rw, p1rb, p1ow);
    topk_kernel<1024><<<BATCH, 512>>>(score, 1024, K1, perm, gain, newid);
    pool_post(K1, 512);

    // ---------- Layer 2 ----------
    gcn(N2, 512, 512, W2, b2);
    bn_pool_pre(N2, 512, g2, be2, p2rw, p2rb, p2ow);
    topk_kernel<1024><<<BATCH, 512>>>(score, K1, K2, perm, gain, newid);
    pool_post(K2, 512);

    // ---------- Layer 3 ----------
    gcn(N3, 512, 256, W3, b3);
    bn_pool_pre(N3, 256, g3, be3, p3rw, p3rb, p3ow);
    topk_kernel<512><<<BATCH, 512>>>(score, K2, K3, perm, gain, newid);
    pool_post(K3, 256);

    // ---------- Layer 4 (no BN / pool) ----------
    gcn(N4, 256, 256, W4, b4);

    // ---------- readout ----------
    readout_kernel<<<BATCH, 256>>>(buf0, out);
    (void)in_sizes; (void)n_in; (void)out_size;
}